// round 9
// baseline (speedup 1.0000x reference)
#include <cuda_runtime.h>
#include <cuda_bf16.h>
#include <cstdint>

#define NN 50000
#define EE 400000
#define HH 128
#define NB 3
#define NITERS 2
#define EPS_ 0.01f

// ---------------- scratch (device globals; no allocation allowed) ----------------
__device__ float g_x[NN * HH];
__device__ float g_v[NN * HH];
__device__ float g_P[NN * HH];
__device__ float g_Q[NN * HH];
__device__ float g_f[NN * HH];
__device__ float g_d[NN * HH];
__device__ float g_g[NN * HH];
__device__ float g_r[EE];
__device__ float g_deg[NN];
// pre-split weights, plain row-major [slot][n][k] bf16 (slot19 = readout, 64x128)
__device__ __nv_bfloat16 g_Wh[20 * 128 * 128];
__device__ __nv_bfloat16 g_Wl[20 * 128 * 128];

__device__ __forceinline__ uint32_t smem_u32(const void* p) {
    uint32_t a;
    asm("{ .reg .u64 t; cvta.to.shared.u64 t, %1; cvt.u32.u64 %0, t; }" : "=r"(a) : "l"(p));
    return a;
}

// ---------------- weight pre-split (runs once per launch) -----------------------
__global__ void convert_weights(const float* __restrict__ emb_w, const float* __restrict__ er_w1,
                                const float* __restrict__ lap_w, const float* __restrict__ diss_w,
                                const float* __restrict__ mlp_w1, const float* __restrict__ mlp_w2,
                                const float* __restrict__ ro_w) {
    int slot = blockIdx.y;
    int rows = (slot == 19) ? 64 : 128;
    int idx = blockIdx.x * 256 + threadIdx.x;
    if (idx >= rows * 128) return;
    int r = idx >> 7, k = idx & 127;
    const float* srcp;
    int wld = 128, koff = 0;
    if (slot == 0) srcp = emb_w;
    else if (slot == 19) srcp = ro_w;
    else {
        int b = (slot - 1) / 6, j = (slot - 1) % 6;
        if (j == 0)      { srcp = er_w1 + (size_t)b * 128 * 256; wld = 256; }
        else if (j == 1) { srcp = er_w1 + (size_t)b * 128 * 256; wld = 256; koff = 128; }
        else if (j == 2) srcp = lap_w  + (size_t)b * 16384;
        else if (j == 3) srcp = diss_w + (size_t)b * 16384;
        else if (j == 4) srcp = mlp_w1 + (size_t)b * 16384;
        else             srcp = mlp_w2 + (size_t)b * 16384;
    }
    float x = srcp[(size_t)r * wld + koff + k];
    __nv_bfloat16 hi = __float2bfloat16(x);
    __nv_bfloat16 lo = __float2bfloat16(x - __bfloat162float(hi));
    g_Wh[slot * 16384 + idx] = hi;
    g_Wl[slot * 16384 + idx] = lo;
}

// ---------------- mma.sync bf16 GEMM: C[M,NOUT] = A[M,128] @ W^T (+bias, act) ---
// double-bf16 split: C = Ah*Bh + Ah*Bl + Al*Bh   (fp32 accumulators)
// 512 threads: warp w -> rows [(w>>1)*16, +16), cols [(w&1)*NOUT/2, +NOUT/2)
// act: 0 none, 1 relu, 2 tanh
#define SPAD 136   // smem row stride in bf16 elems (272 B -> conflict-free LDSM)
template <int NOUT>
__global__ void __launch_bounds__(512)
gemm_tc(const float* __restrict__ A, int M,
        const __nv_bfloat16* __restrict__ Bh, const __nv_bfloat16* __restrict__ Bl,
        const float* __restrict__ bias, int act, float* __restrict__ C) {
    constexpr int NT = NOUT / 16;     // n8-tiles per warp (half the columns)
    extern __shared__ char sm[];
    float* sbias = (float*)sm;                               // [NOUT]
    __nv_bfloat16* sAh = (__nv_bfloat16*)(sm + 1024);        // [128][SPAD]
    __nv_bfloat16* sAl = sAh + 128 * SPAD;
    __nv_bfloat16* sBh = sAl + 128 * SPAD;                   // [NOUT][SPAD]
    __nv_bfloat16* sBl = sBh + NOUT * SPAD;

    int tid = threadIdx.x, wid = tid >> 5, lane = tid & 31;
    int mband = wid >> 1, nhalf = wid & 1;
    int r0 = blockIdx.x * 128;

    // B: copy pre-split weights (row-major) into padded smem
    for (int i = tid; i < NOUT * 64; i += 512) {
        int n = i >> 6, kp = (i & 63);
        ((uint32_t*)(sBh + n * SPAD))[kp] = ((const uint32_t*)(Bh + n * 128))[kp];
        ((uint32_t*)(sBl + n * SPAD))[kp] = ((const uint32_t*)(Bl + n * 128))[kp];
    }
    if (tid < NOUT) sbias[tid] = bias ? bias[tid] : 0.f;

    // A: load fp32, split hi/lo bf16 into padded smem
    for (int i = tid; i < 128 * 64; i += 512) {
        int row = i >> 6, k = (i & 63) << 1;
        float2 a = make_float2(0.f, 0.f);
        if (r0 + row < M) a = *(const float2*)(A + (size_t)(r0 + row) * 128 + k);
        __nv_bfloat16 h0 = __float2bfloat16(a.x);
        __nv_bfloat16 h1 = __float2bfloat16(a.y);
        __nv_bfloat162 hp; hp.x = h0; hp.y = h1;
        __nv_bfloat162 lp;
        lp.x = __float2bfloat16(a.x - __bfloat162float(h0));
        lp.y = __float2bfloat16(a.y - __bfloat162float(h1));
        *(__nv_bfloat162*)(sAh + row * SPAD + k) = hp;
        *(__nv_bfloat162*)(sAl + row * SPAD + k) = lp;
    }
    __syncthreads();

    float acc[NT][4];
#pragma unroll
    for (int t = 0; t < NT; t++)
#pragma unroll
        for (int j = 0; j < 4; j++) acc[t][j] = 0.f;

    // ldmatrix base addresses (lane-dependent row/col mapping)
    // A (.x4, m16k16): row = mband*16 + lane%16, kcol = (lane/16)*8
    uint32_t aRow = mband * 16 + (lane & 15), aCol = (lane >> 4) << 3;
    // B (.x4, two n8-tiles x k16): n = nhalf*NOUT/2 + (lane>>4)*8 + (lane&7)
    uint32_t bRow = nhalf * (NOUT / 2) + ((lane >> 4) << 3) + (lane & 7);
    uint32_t bCol = ((lane >> 3) & 1) << 3;

#pragma unroll
    for (int term = 0; term < 3; term++) {
        const __nv_bfloat16* pA = (term == 2) ? sAl : sAh;
        const __nv_bfloat16* pB = (term == 1) ? sBl : sBh;
        uint32_t aBase = smem_u32(pA) + (aRow * SPAD + aCol) * 2;
        uint32_t bBase = smem_u32(pB) + (bRow * SPAD + bCol) * 2;
#pragma unroll
        for (int kk = 0; kk < 8; kk++) {
            uint32_t a0, a1, a2, a3;
            asm volatile("ldmatrix.sync.aligned.m8n8.x4.shared.b16 {%0,%1,%2,%3}, [%4];"
                         : "=r"(a0), "=r"(a1), "=r"(a2), "=r"(a3)
                         : "r"(aBase + kk * 32));
#pragma unroll
            for (int np = 0; np < NT / 2; np++) {
                uint32_t b0, b1, b2, b3;
                asm volatile("ldmatrix.sync.aligned.m8n8.x4.shared.b16 {%0,%1,%2,%3}, [%4];"
                             : "=r"(b0), "=r"(b1), "=r"(b2), "=r"(b3)
                             : "r"(bBase + (np * 16 * SPAD) * 2 + kk * 32));
                asm volatile(
                    "mma.sync.aligned.m16n8k16.row.col.f32.bf16.bf16.f32 "
                    "{%0,%1,%2,%3}, {%4,%5,%6,%7}, {%8,%9}, {%0,%1,%2,%3};"
                    : "+f"(acc[np * 2][0]), "+f"(acc[np * 2][1]),
                      "+f"(acc[np * 2][2]), "+f"(acc[np * 2][3])
                    : "r"(a0), "r"(a1), "r"(a2), "r"(a3), "r"(b0), "r"(b1));
                asm volatile(
                    "mma.sync.aligned.m16n8k16.row.col.f32.bf16.bf16.f32 "
                    "{%0,%1,%2,%3}, {%4,%5,%6,%7}, {%8,%9}, {%0,%1,%2,%3};"
                    : "+f"(acc[np * 2 + 1][0]), "+f"(acc[np * 2 + 1][1]),
                      "+f"(acc[np * 2 + 1][2]), "+f"(acc[np * 2 + 1][3])
                    : "r"(a0), "r"(a1), "r"(a2), "r"(a3), "r"(b2), "r"(b3));
            }
        }
    }

    // epilogue: c fragment (r=lane/4 [+8], n=2*(lane%4)+{0,1}) per n-tile
    int rA = r0 + mband * 16 + (lane >> 2);
    int cB = 2 * (lane & 3);
#pragma unroll
    for (int t = 0; t < NT; t++) {
        int col = nhalf * (NOUT / 2) + t * 8 + cB;
        float2 u0 = make_float2(acc[t][0] + sbias[col], acc[t][1] + sbias[col + 1]);
        float2 u1 = make_float2(acc[t][2] + sbias[col], acc[t][3] + sbias[col + 1]);
        if (act == 1) {
            u0.x = fmaxf(u0.x, 0.f); u0.y = fmaxf(u0.y, 0.f);
            u1.x = fmaxf(u1.x, 0.f); u1.y = fmaxf(u1.y, 0.f);
        } else if (act == 2) {
            u0.x = tanhf(u0.x); u0.y = tanhf(u0.y);
            u1.x = tanhf(u1.x); u1.y = tanhf(u1.y);
        }
        if (rA < M)     *(float2*)(C + (size_t)rA * NOUT + col) = u0;
        if (rA + 8 < M) *(float2*)(C + (size_t)(rA + 8) * NOUT + col) = u1;
    }
}

// ---------------- edge resistance (unchanged) -----------------------------------
__global__ void __launch_bounds__(256)
edge_resist(const int* __restrict__ src, const int* __restrict__ dst,
            const float* __restrict__ b1, const float* __restrict__ w2,
            const float* __restrict__ b2) {
    int e = (blockIdx.x * blockDim.x + threadIdx.x) >> 5;
    int lane = threadIdx.x & 31;
    if (e >= EE) return;
    int s = src[e], d = dst[e];
    float4 p = *(const float4*)(g_P + (size_t)s * HH + lane * 4);
    float4 q = *(const float4*)(g_Q + (size_t)d * HH + lane * 4);
    float4 bb = *(const float4*)(b1 + lane * 4);
    float4 ww = *(const float4*)(w2 + lane * 4);
    float sum = fmaxf(p.x + q.x + bb.x, 0.f) * ww.x
              + fmaxf(p.y + q.y + bb.y, 0.f) * ww.y
              + fmaxf(p.z + q.z + bb.z, 0.f) * ww.z
              + fmaxf(p.w + q.w + bb.w, 0.f) * ww.w;
#pragma unroll
    for (int off = 16; off > 0; off >>= 1) sum += __shfl_xor_sync(0xFFFFFFFFu, sum, off);
    if (lane == 0) {
        float rr = fabsf(sum + b2[0]);
        g_r[e] = rr;
        atomicAdd(&g_deg[s], rr);
    }
}

// ---------------- scatter (unchanged) -------------------------------------------
__global__ void __launch_bounds__(256)
scatter_edges(const int* __restrict__ src, const int* __restrict__ dst) {
    int e = (blockIdx.x * blockDim.x + threadIdx.x) >> 5;
    int lane = threadIdx.x & 31;
    if (e >= EE) return;
    float rr = g_r[e];
    int s = src[e], d = dst[e];
    float4 fv = *(const float4*)(g_f + (size_t)s * HH + lane * 4);
    float* gp = g_g + (size_t)d * HH + lane * 4;
    asm volatile("red.global.add.v4.f32 [%0], {%1,%2,%3,%4};"
                 :: "l"(gp), "f"(rr * fv.x), "f"(rr * fv.y), "f"(rr * fv.z), "f"(rr * fv.w)
                 : "memory");
}

// ---------------- node update (unchanged) ---------------------------------------
__global__ void __launch_bounds__(256)
update_nodes() {
    int i4 = blockIdx.x * blockDim.x + threadIdx.x;
    if (i4 >= NN * HH / 4) return;
    int row = i4 >> 5;
    float dg = g_deg[row];
    float4 f4 = ((const float4*)g_f)[i4];
    float4 gg = ((const float4*)g_g)[i4];
    float4 ds = ((const float4*)g_d)[i4];
    float4 vv = ((const float4*)g_v)[i4];
    float4 xx = ((const float4*)g_x)[i4];
    vv.x -= EPS_ * ((dg * f4.x - gg.x) + ds.x * vv.x);
    vv.y -= EPS_ * ((dg * f4.y - gg.y) + ds.y * vv.y);
    vv.z -= EPS_ * ((dg * f4.z - gg.z) + ds.z * vv.z);
    vv.w -= EPS_ * ((dg * f4.w - gg.w) + ds.w * vv.w);
    xx.x += EPS_ * vv.x;
    xx.y += EPS_ * vv.y;
    xx.z += EPS_ * vv.z;
    xx.w += EPS_ * vv.w;
    ((float4*)g_v)[i4] = vv;
    ((float4*)g_x)[i4] = xx;
}

// ------------------------------- driver -----------------------------------------
extern "C" void kernel_launch(void* const* d_in, const int* in_sizes, int n_in,
                              void* d_out, int out_size) {
    const float* x_in   = (const float*)d_in[0];
    const int*   ei     = (const int*)  d_in[1];
    const float* emb_w  = (const float*)d_in[2];
    const float* emb_b  = (const float*)d_in[3];
    const float* lap_w  = (const float*)d_in[4];
    const float* er_w1  = (const float*)d_in[5];
    const float* er_b1  = (const float*)d_in[6];
    const float* er_w2  = (const float*)d_in[7];
    const float* er_b2  = (const float*)d_in[8];
    const float* diss_w = (const float*)d_in[9];
    const float* diss_b = (const float*)d_in[10];
    const float* mlp_w1 = (const float*)d_in[11];
    const float* mlp_b1 = (const float*)d_in[12];
    const float* mlp_w2 = (const float*)d_in[13];
    const float* mlp_b2 = (const float*)d_in[14];
    const float* ro_w   = (const float*)d_in[15];
    const float* ro_b   = (const float*)d_in[16];
    const int* src = ei;
    const int* dst = ei + EE;

    float *px, *pv, *pP, *pQ, *pf, *pd, *pg, *pdeg;
    cudaGetSymbolAddress((void**)&px, g_x);
    cudaGetSymbolAddress((void**)&pv, g_v);
    cudaGetSymbolAddress((void**)&pP, g_P);
    cudaGetSymbolAddress((void**)&pQ, g_Q);
    cudaGetSymbolAddress((void**)&pf, g_f);
    cudaGetSymbolAddress((void**)&pd, g_d);
    cudaGetSymbolAddress((void**)&pg, g_g);
    cudaGetSymbolAddress((void**)&pdeg, g_deg);
    __nv_bfloat16 *pWh, *pWl;
    cudaGetSymbolAddress((void**)&pWh, g_Wh);
    cudaGetSymbolAddress((void**)&pWl, g_Wl);

    // smem: 1024 (bias) + 2*128*SPAD*2 (A) + 2*NOUT*SPAD*2 (B)
    const int SMT128 = 1024 + 2 * 128 * SPAD * 2 + 2 * 128 * SPAD * 2;  // 140288
    const int SMT64  = 1024 + 2 * 128 * SPAD * 2 + 2 * 64 * SPAD * 2;   // 105472
    cudaFuncSetAttribute(gemm_tc<128>, cudaFuncAttributeMaxDynamicSharedMemorySize, SMT128);
    cudaFuncSetAttribute(gemm_tc<64>,  cudaFuncAttributeMaxDynamicSharedMemorySize, SMT64);

    const int GT = (NN + 127) / 128;   // 391
    const int EB = EE / 8;
    const int UB = (NN * HH / 4 + 255) / 256;
#define WSLOT(s) (pWh + (s) * 16384), (pWl + (s) * 16384)

    convert_weights<<<dim3(64, 20), 256>>>(emb_w, er_w1, lap_w, diss_w, mlp_w1, mlp_w2, ro_w);

    // x = x_in @ emb_w^T + emb_b
    gemm_tc<128><<<GT, 512, SMT128>>>(x_in, NN, WSLOT(0), emb_b, 0, px);

    for (int b = 0; b < NB; b++) {
        int s0 = 1 + b * 6;
        gemm_tc<128><<<GT, 512, SMT128>>>(px, NN, WSLOT(s0 + 0), nullptr, 0, pP);
        gemm_tc<128><<<GT, 512, SMT128>>>(px, NN, WSLOT(s0 + 1), nullptr, 0, pQ);
        cudaMemsetAsync(pdeg, 0, NN * sizeof(float), 0);
        cudaMemsetAsync(pv, 0, (size_t)NN * HH * sizeof(float), 0);
        edge_resist<<<EB, 256>>>(src, dst, er_b1 + (size_t)b * HH,
                                 er_w2 + (size_t)b * HH, er_b2 + b);
        for (int it = 0; it < NITERS; it++) {
            gemm_tc<128><<<GT, 512, SMT128>>>(px, NN, WSLOT(s0 + 2), nullptr, 0, pf);
            gemm_tc<128><<<GT, 512, SMT128>>>(px, NN, WSLOT(s0 + 3),
                                              diss_b + (size_t)b * HH, 1, pd);
            cudaMemsetAsync(pg, 0, (size_t)NN * HH * sizeof(float), 0);
            scatter_edges<<<EB, 256>>>(src, dst);
            update_nodes<<<UB, 256>>>();
        }
        gemm_tc<128><<<GT, 512, SMT128>>>(px, NN, WSLOT(s0 + 4),
                                          mlp_b1 + (size_t)b * HH, 2, pP);
        gemm_tc<128><<<GT, 512, SMT128>>>(pP, NN, WSLOT(s0 + 5),
                                          mlp_b2 + (size_t)b * HH, 0, px);
    }

    gemm_tc<64><<<GT, 512, SMT64>>>(px, NN, WSLOT(19), ro_b, 0, (float*)d_out);
}

// round 11
// speedup vs baseline: 1.1064x; 1.1064x over previous
#include <cuda_runtime.h>
#include <cuda_bf16.h>
#include <cstdint>

#define NN 50000
#define EE 400000
#define HH 128
#define NB 3
#define NITERS 2
#define EPS_ 0.01f

// ---------------- scratch (device globals; no allocation allowed) ----------------
__device__ float g_x[NN * HH];
__device__ float g_v[NN * HH];
__device__ float g_P[NN * HH];
__device__ float g_Q[NN * HH];
__device__ float g_f[NN * HH];
__device__ float g_d[NN * HH];
__device__ float g_g[NN * HH];
__device__ float g_r[EE];
__device__ float g_deg[NN];
// pre-split weights, plain row-major [slot][n][k] bf16 (slot19 = readout, 64x128)
__device__ __nv_bfloat16 g_Wh[20 * 128 * 128];
__device__ __nv_bfloat16 g_Wl[20 * 128 * 128];

__device__ __forceinline__ uint32_t smem_u32(const void* p) {
    uint32_t a;
    asm("{ .reg .u64 t; cvta.to.shared.u64 t, %1; cvt.u32.u64 %0, t; }" : "=r"(a) : "l"(p));
    return a;
}

// ---------------- weight pre-split (runs once per launch) -----------------------
__global__ void convert_weights(const float* __restrict__ emb_w, const float* __restrict__ er_w1,
                                const float* __restrict__ lap_w, const float* __restrict__ diss_w,
                                const float* __restrict__ mlp_w1, const float* __restrict__ mlp_w2,
                                const float* __restrict__ ro_w) {
    int slot = blockIdx.y;
    int rows = (slot == 19) ? 64 : 128;
    int idx = blockIdx.x * 256 + threadIdx.x;
    if (idx >= rows * 128) return;
    int r = idx >> 7, k = idx & 127;
    const float* srcp;
    int wld = 128, koff = 0;
    if (slot == 0) srcp = emb_w;
    else if (slot == 19) srcp = ro_w;
    else {
        int b = (slot - 1) / 6, j = (slot - 1) % 6;
        if (j == 0)      { srcp = er_w1 + (size_t)b * 128 * 256; wld = 256; }
        else if (j == 1) { srcp = er_w1 + (size_t)b * 128 * 256; wld = 256; koff = 128; }
        else if (j == 2) srcp = lap_w  + (size_t)b * 16384;
        else if (j == 3) srcp = diss_w + (size_t)b * 16384;
        else if (j == 4) srcp = mlp_w1 + (size_t)b * 16384;
        else             srcp = mlp_w2 + (size_t)b * 16384;
    }
    float x = srcp[(size_t)r * wld + koff + k];
    __nv_bfloat16 hi = __float2bfloat16(x);
    __nv_bfloat16 lo = __float2bfloat16(x - __bfloat162float(hi));
    g_Wh[slot * 16384 + idx] = hi;
    g_Wl[slot * 16384 + idx] = lo;
}

// ---------------- mma.sync bf16 GEMM: C[M,NOUT] = A[M,128] @ W^T (+bias, act) ---
// double-bf16 split: C = Ah*Bh + Ah*Bl + Al*Bh   (fp32 accumulators)
// 64-row tile, 256 threads: warp w -> rows [(w>>1)*16,+16), cols [(w&1)*NOUT/2,+NOUT/2)
// smem ~105 KB -> 2 CTAs/SM (4 warps/SMSP), no register spills.
// act: 0 none, 1 relu, 2 tanh
#define SPAD 136   // smem row stride in bf16 elems (272 B -> conflict-free LDSM)
template <int NOUT>
__global__ void __launch_bounds__(256, 2)
gemm_tc(const float* __restrict__ A, int M,
        const __nv_bfloat16* __restrict__ Bh, const __nv_bfloat16* __restrict__ Bl,
        const float* __restrict__ bias, int act, float* __restrict__ C) {
    constexpr int NT = NOUT / 16;     // n8-tiles per warp (half the columns)
    extern __shared__ char sm[];
    float* sbias = (float*)sm;                               // [NOUT]
    __nv_bfloat16* sAh = (__nv_bfloat16*)(sm + 1024);        // [64][SPAD]
    __nv_bfloat16* sAl = sAh + 64 * SPAD;
    __nv_bfloat16* sBh = sAl + 64 * SPAD;                    // [NOUT][SPAD]
    __nv_bfloat16* sBl = sBh + NOUT * SPAD;

    int tid = threadIdx.x, wid = tid >> 5, lane = tid & 31;
    int mband = wid >> 1, nhalf = wid & 1;
    int r0 = blockIdx.x * 64;

    // B: copy pre-split weights (row-major) into padded smem
    for (int i = tid; i < NOUT * 64; i += 256) {
        int n = i >> 6, kp = (i & 63);
        ((uint32_t*)(sBh + n * SPAD))[kp] = ((const uint32_t*)(Bh + n * 128))[kp];
        ((uint32_t*)(sBl + n * SPAD))[kp] = ((const uint32_t*)(Bl + n * 128))[kp];
    }
    if (tid < NOUT) sbias[tid] = bias ? bias[tid] : 0.f;

    // A: load fp32, split hi/lo bf16 into padded smem (64 rows)
    for (int i = tid; i < 64 * 64; i += 256) {
        int row = i >> 6, k = (i & 63) << 1;
        float2 a = make_float2(0.f, 0.f);
        if (r0 + row < M) a = *(const float2*)(A + (size_t)(r0 + row) * 128 + k);
        __nv_bfloat16 h0 = __float2bfloat16(a.x);
        __nv_bfloat16 h1 = __float2bfloat16(a.y);
        __nv_bfloat162 hp; hp.x = h0; hp.y = h1;
        __nv_bfloat162 lp;
        lp.x = __float2bfloat16(a.x - __bfloat162float(h0));
        lp.y = __float2bfloat16(a.y - __bfloat162float(h1));
        *(__nv_bfloat162*)(sAh + row * SPAD + k) = hp;
        *(__nv_bfloat162*)(sAl + row * SPAD + k) = lp;
    }
    __syncthreads();

    float acc[NT][4];
#pragma unroll
    for (int t = 0; t < NT; t++)
#pragma unroll
        for (int j = 0; j < 4; j++) acc[t][j] = 0.f;

    // ldmatrix base addresses (lane-dependent row/col mapping)
    // A (.x4, m16k16): row = mband*16 + lane%16, kcol = (lane/16)*8
    uint32_t aRow = mband * 16 + (lane & 15), aCol = (lane >> 4) << 3;
    // B (.x4, two n8-tiles x k16): n = nhalf*NOUT/2 + (lane>>4)*8 + (lane&7)
    uint32_t bRow = nhalf * (NOUT / 2) + ((lane >> 4) << 3) + (lane & 7);
    uint32_t bCol = ((lane >> 3) & 1) << 3;

#pragma unroll
    for (int term = 0; term < 3; term++) {
        const __nv_bfloat16* pA = (term == 2) ? sAl : sAh;
        const __nv_bfloat16* pB = (term == 1) ? sBl : sBh;
        uint32_t aBase = smem_u32(pA) + (aRow * SPAD + aCol) * 2;
        uint32_t bBase = smem_u32(pB) + (bRow * SPAD + bCol) * 2;
#pragma unroll
        for (int kk = 0; kk < 8; kk++) {
            uint32_t a0, a1, a2, a3;
            asm volatile("ldmatrix.sync.aligned.m8n8.x4.shared.b16 {%0,%1,%2,%3}, [%4];"
                         : "=r"(a0), "=r"(a1), "=r"(a2), "=r"(a3)
                         : "r"(aBase + kk * 32));
#pragma unroll
            for (int np = 0; np < NT / 2; np++) {
                uint32_t b0, b1, b2, b3;
                asm volatile("ldmatrix.sync.aligned.m8n8.x4.shared.b16 {%0,%1,%2,%3}, [%4];"
                             : "=r"(b0), "=r"(b1), "=r"(b2), "=r"(b3)
                             : "r"(bBase + (np * 16 * SPAD) * 2 + kk * 32));
                asm volatile(
                    "mma.sync.aligned.m16n8k16.row.col.f32.bf16.bf16.f32 "
                    "{%0,%1,%2,%3}, {%4,%5,%6,%7}, {%8,%9}, {%0,%1,%2,%3};"
                    : "+f"(acc[np * 2][0]), "+f"(acc[np * 2][1]),
                      "+f"(acc[np * 2][2]), "+f"(acc[np * 2][3])
                    : "r"(a0), "r"(a1), "r"(a2), "r"(a3), "r"(b0), "r"(b1));
                asm volatile(
                    "mma.sync.aligned.m16n8k16.row.col.f32.bf16.bf16.f32 "
                    "{%0,%1,%2,%3}, {%4,%5,%6,%7}, {%8,%9}, {%0,%1,%2,%3};"
                    : "+f"(acc[np * 2 + 1][0]), "+f"(acc[np * 2 + 1][1]),
                      "+f"(acc[np * 2 + 1][2]), "+f"(acc[np * 2 + 1][3])
                    : "r"(a0), "r"(a1), "r"(a2), "r"(a3), "r"(b2), "r"(b3));
            }
        }
    }

    // epilogue: c fragment (r=lane/4 [+8], n=2*(lane%4)+{0,1}) per n-tile
    int rA = r0 + mband * 16 + (lane >> 2);
    int cB = 2 * (lane & 3);
#pragma unroll
    for (int t = 0; t < NT; t++) {
        int col = nhalf * (NOUT / 2) + t * 8 + cB;
        float2 u0 = make_float2(acc[t][0] + sbias[col], acc[t][1] + sbias[col + 1]);
        float2 u1 = make_float2(acc[t][2] + sbias[col], acc[t][3] + sbias[col + 1]);
        if (act == 1) {
            u0.x = fmaxf(u0.x, 0.f); u0.y = fmaxf(u0.y, 0.f);
            u1.x = fmaxf(u1.x, 0.f); u1.y = fmaxf(u1.y, 0.f);
        } else if (act == 2) {
            u0.x = tanhf(u0.x); u0.y = tanhf(u0.y);
            u1.x = tanhf(u1.x); u1.y = tanhf(u1.y);
        }
        if (rA < M)     *(float2*)(C + (size_t)rA * NOUT + col) = u0;
        if (rA + 8 < M) *(float2*)(C + (size_t)(rA + 8) * NOUT + col) = u1;
    }
}

// ---------------- edge resistance (unchanged) -----------------------------------
__global__ void __launch_bounds__(256)
edge_resist(const int* __restrict__ src, const int* __restrict__ dst,
            const float* __restrict__ b1, const float* __restrict__ w2,
            const float* __restrict__ b2) {
    int e = (blockIdx.x * blockDim.x + threadIdx.x) >> 5;
    int lane = threadIdx.x & 31;
    if (e >= EE) return;
    int s = src[e], d = dst[e];
    float4 p = *(const float4*)(g_P + (size_t)s * HH + lane * 4);
    float4 q = *(const float4*)(g_Q + (size_t)d * HH + lane * 4);
    float4 bb = *(const float4*)(b1 + lane * 4);
    float4 ww = *(const float4*)(w2 + lane * 4);
    float sum = fmaxf(p.x + q.x + bb.x, 0.f) * ww.x
              + fmaxf(p.y + q.y + bb.y, 0.f) * ww.y
              + fmaxf(p.z + q.z + bb.z, 0.f) * ww.z
              + fmaxf(p.w + q.w + bb.w, 0.f) * ww.w;
#pragma unroll
    for (int off = 16; off > 0; off >>= 1) sum += __shfl_xor_sync(0xFFFFFFFFu, sum, off);
    if (lane == 0) {
        float rr = fabsf(sum + b2[0]);
        g_r[e] = rr;
        atomicAdd(&g_deg[s], rr);
    }
}

// ---------------- scatter (unchanged) -------------------------------------------
__global__ void __launch_bounds__(256)
scatter_edges(const int* __restrict__ src, const int* __restrict__ dst) {
    int e = (blockIdx.x * blockDim.x + threadIdx.x) >> 5;
    int lane = threadIdx.x & 31;
    if (e >= EE) return;
    float rr = g_r[e];
    int s = src[e], d = dst[e];
    float4 fv = *(const float4*)(g_f + (size_t)s * HH + lane * 4);
    float* gp = g_g + (size_t)d * HH + lane * 4;
    asm volatile("red.global.add.v4.f32 [%0], {%1,%2,%3,%4};"
                 :: "l"(gp), "f"(rr * fv.x), "f"(rr * fv.y), "f"(rr * fv.z), "f"(rr * fv.w)
                 : "memory");
}

// ---------------- node update (unchanged) ---------------------------------------
__global__ void __launch_bounds__(256)
update_nodes() {
    int i4 = blockIdx.x * blockDim.x + threadIdx.x;
    if (i4 >= NN * HH / 4) return;
    int row = i4 >> 5;
    float dg = g_deg[row];
    float4 f4 = ((const float4*)g_f)[i4];
    float4 gg = ((const float4*)g_g)[i4];
    float4 ds = ((const float4*)g_d)[i4];
    float4 vv = ((const float4*)g_v)[i4];
    float4 xx = ((const float4*)g_x)[i4];
    vv.x -= EPS_ * ((dg * f4.x - gg.x) + ds.x * vv.x);
    vv.y -= EPS_ * ((dg * f4.y - gg.y) + ds.y * vv.y);
    vv.z -= EPS_ * ((dg * f4.z - gg.z) + ds.z * vv.z);
    vv.w -= EPS_ * ((dg * f4.w - gg.w) + ds.w * vv.w);
    xx.x += EPS_ * vv.x;
    xx.y += EPS_ * vv.y;
    xx.z += EPS_ * vv.z;
    xx.w += EPS_ * vv.w;
    ((float4*)g_v)[i4] = vv;
    ((float4*)g_x)[i4] = xx;
}

// ------------------------------- driver -----------------------------------------
extern "C" void kernel_launch(void* const* d_in, const int* in_sizes, int n_in,
                              void* d_out, int out_size) {
    const float* x_in   = (const float*)d_in[0];
    const int*   ei     = (const int*)  d_in[1];
    const float* emb_w  = (const float*)d_in[2];
    const float* emb_b  = (const float*)d_in[3];
    const float* lap_w  = (const float*)d_in[4];
    const float* er_w1  = (const float*)d_in[5];
    const float* er_b1  = (const float*)d_in[6];
    const float* er_w2  = (const float*)d_in[7];
    const float* er_b2  = (const float*)d_in[8];
    const float* diss_w = (const float*)d_in[9];
    const float* diss_b = (const float*)d_in[10];
    const float* mlp_w1 = (const float*)d_in[11];
    const float* mlp_b1 = (const float*)d_in[12];
    const float* mlp_w2 = (const float*)d_in[13];
    const float* mlp_b2 = (const float*)d_in[14];
    const float* ro_w   = (const float*)d_in[15];
    const float* ro_b   = (const float*)d_in[16];
    const int* src = ei;
    const int* dst = ei + EE;

    float *px, *pv, *pP, *pQ, *pf, *pd, *pg, *pdeg;
    cudaGetSymbolAddress((void**)&px, g_x);
    cudaGetSymbolAddress((void**)&pv, g_v);
    cudaGetSymbolAddress((void**)&pP, g_P);
    cudaGetSymbolAddress((void**)&pQ, g_Q);
    cudaGetSymbolAddress((void**)&pf, g_f);
    cudaGetSymbolAddress((void**)&pd, g_d);
    cudaGetSymbolAddress((void**)&pg, g_g);
    cudaGetSymbolAddress((void**)&pdeg, g_deg);
    __nv_bfloat16 *pWh, *pWl;
    cudaGetSymbolAddress((void**)&pWh, g_Wh);
    cudaGetSymbolAddress((void**)&pWl, g_Wl);

    // smem: 1024 (bias) + 2*64*SPAD*2 (A) + 2*NOUT*SPAD*2 (B)
    const int SMT128 = 1024 + 2 * 64 * SPAD * 2 + 2 * 128 * SPAD * 2;  // 105472
    const int SMT64  = 1024 + 2 * 64 * SPAD * 2 + 2 * 64 * SPAD * 2;   // 70656
    cudaFuncSetAttribute(gemm_tc<128>, cudaFuncAttributeMaxDynamicSharedMemorySize, SMT128);
    cudaFuncSetAttribute(gemm_tc<64>,  cudaFuncAttributeMaxDynamicSharedMemorySize, SMT64);

    const int GT = (NN + 63) / 64;     // 782
    const int EB = EE / 8;
    const int UB = (NN * HH / 4 + 255) / 256;
#define WSLOT(s) (pWh + (s) * 16384), (pWl + (s) * 16384)

    convert_weights<<<dim3(64, 20), 256>>>(emb_w, er_w1, lap_w, diss_w, mlp_w1, mlp_w2, ro_w);

    // x = x_in @ emb_w^T + emb_b
    gemm_tc<128><<<GT, 256, SMT128>>>(x_in, NN, WSLOT(0), emb_b, 0, px);

    for (int b = 0; b < NB; b++) {
        int s0 = 1 + b * 6;
        gemm_tc<128><<<GT, 256, SMT128>>>(px, NN, WSLOT(s0 + 0), nullptr, 0, pP);
        gemm_tc<128><<<GT, 256, SMT128>>>(px, NN, WSLOT(s0 + 1), nullptr, 0, pQ);
        cudaMemsetAsync(pdeg, 0, NN * sizeof(float), 0);
        cudaMemsetAsync(pv, 0, (size_t)NN * HH * sizeof(float), 0);
        edge_resist<<<EB, 256>>>(src, dst, er_b1 + (size_t)b * HH,
                                 er_w2 + (size_t)b * HH, er_b2 + b);
        for (int it = 0; it < NITERS; it++) {
            gemm_tc<128><<<GT, 256, SMT128>>>(px, NN, WSLOT(s0 + 2), nullptr, 0, pf);
            gemm_tc<128><<<GT, 256, SMT128>>>(px, NN, WSLOT(s0 + 3),
                                              diss_b + (size_t)b * HH, 1, pd);
            cudaMemsetAsync(pg, 0, (size_t)NN * HH * sizeof(float), 0);
            scatter_edges<<<EB, 256>>>(src, dst);
            update_nodes<<<UB, 256>>>();
        }
        gemm_tc<128><<<GT, 256, SMT128>>>(px, NN, WSLOT(s0 + 4),
                                          mlp_b1 + (size_t)b * HH, 2, pP);
        gemm_tc<128><<<GT, 256, SMT128>>>(pP, NN, WSLOT(s0 + 5),
                                          mlp_b2 + (size_t)b * HH, 0, px);
    }

    gemm_tc<64><<<GT, 256, SMT64>>>(px, NN, WSLOT(19), ro_b, 0, (float*)d_out);
}

// round 12
// speedup vs baseline: 1.2801x; 1.1569x over previous
#include <cuda_runtime.h>
#include <cuda_bf16.h>
#include <cstdint>

#define NN 50000
#define EE 400000
#define HH 128
#define NB 3
#define NITERS 2
#define EPS_ 0.01f

// ---------------- scratch (device globals; no allocation allowed) ----------------
__device__ float g_x[NN * HH];
__device__ float g_v[NN * HH];
__device__ float g_P[NN * HH];
__device__ float g_Q[NN * HH];
__device__ float g_f[NN * HH];
__device__ float g_d[NN * HH];
__device__ float g_g[NN * HH];
__device__ float g_r[EE];
__device__ float g_deg[NN];
// pre-split weights, plain row-major [slot][n][k] bf16 (slot19 = readout, 64x128)
__device__ __nv_bfloat16 g_Wh[20 * 128 * 128];
__device__ __nv_bfloat16 g_Wl[20 * 128 * 128];

__device__ __forceinline__ uint32_t smem_u32(const void* p) {
    uint32_t a;
    asm("{ .reg .u64 t; cvta.to.shared.u64 t, %1; cvt.u32.u64 %0, t; }" : "=r"(a) : "l"(p));
    return a;
}

// ---------------- weight pre-split (runs once per launch) -----------------------
__global__ void convert_weights(const float* __restrict__ emb_w, const float* __restrict__ er_w1,
                                const float* __restrict__ lap_w, const float* __restrict__ diss_w,
                                const float* __restrict__ mlp_w1, const float* __restrict__ mlp_w2,
                                const float* __restrict__ ro_w) {
    int slot = blockIdx.y;
    int rows = (slot == 19) ? 64 : 128;
    int idx = blockIdx.x * 256 + threadIdx.x;
    if (idx >= rows * 128) return;
    int r = idx >> 7, k = idx & 127;
    const float* srcp;
    int wld = 128, koff = 0;
    if (slot == 0) srcp = emb_w;
    else if (slot == 19) srcp = ro_w;
    else {
        int b = (slot - 1) / 6, j = (slot - 1) % 6;
        if (j == 0)      { srcp = er_w1 + (size_t)b * 128 * 256; wld = 256; }
        else if (j == 1) { srcp = er_w1 + (size_t)b * 128 * 256; wld = 256; koff = 128; }
        else if (j == 2) srcp = lap_w  + (size_t)b * 16384;
        else if (j == 3) srcp = diss_w + (size_t)b * 16384;
        else if (j == 4) srcp = mlp_w1 + (size_t)b * 16384;
        else             srcp = mlp_w2 + (size_t)b * 16384;
    }
    float x = srcp[(size_t)r * wld + koff + k];
    __nv_bfloat16 hi = __float2bfloat16(x);
    __nv_bfloat16 lo = __float2bfloat16(x - __bfloat162float(hi));
    g_Wh[slot * 16384 + idx] = hi;
    g_Wl[slot * 16384 + idx] = lo;
}

// ---------------- mma.sync bf16 GEMM: C[M,NOUT] = A[M,128] @ W^T (+bias, act) ---
// TERMS=3: double-bf16 split  C = Ah*Bh + Ah*Bl + Al*Bh   (~1e-5 accuracy)
// TERMS=1: plain bf16         C = Ah*Bh                   (~4e-3; for eps-damped paths)
// 64-row tile, 256 threads: warp w -> rows [(w>>1)*16,+16), cols [(w&1)*NOUT/2,+NOUT/2)
// act: 0 none, 1 relu, 2 tanh
#define SPAD 136   // smem row stride in bf16 elems (272 B -> conflict-free LDSM)
template <int NOUT, int TERMS>
__global__ void __launch_bounds__(256, 2)
gemm_tc(const float* __restrict__ A, int M,
        const __nv_bfloat16* __restrict__ Bh, const __nv_bfloat16* __restrict__ Bl,
        const float* __restrict__ bias, int act, float* __restrict__ C) {
    constexpr int NT = NOUT / 16;          // n8-tiles per warp (half the columns)
    constexpr int NA = (TERMS == 3) ? 2 : 1;
    constexpr int A_SZ = 64 * SPAD * 2;    // bytes per A tile
    constexpr int B_SZ = NOUT * SPAD * 2;  // bytes per B tile
    extern __shared__ char sm[];
    float* sbias = (float*)sm;                                   // [NOUT]
    __nv_bfloat16* sAh = (__nv_bfloat16*)(sm + 1024);            // [64][SPAD]
    __nv_bfloat16* sAl = (__nv_bfloat16*)(sm + 1024 + A_SZ);     // TERMS==3 only
    __nv_bfloat16* sBh = (__nv_bfloat16*)(sm + 1024 + NA * A_SZ);
    __nv_bfloat16* sBl = (__nv_bfloat16*)(sm + 1024 + NA * A_SZ + B_SZ);

    int tid = threadIdx.x, wid = tid >> 5, lane = tid & 31;
    int mband = wid >> 1, nhalf = wid & 1;
    int r0 = blockIdx.x * 64;

    // B: copy pre-split weights (row-major) into padded smem
    for (int i = tid; i < NOUT * 64; i += 256) {
        int n = i >> 6, kp = (i & 63);
        ((uint32_t*)(sBh + n * SPAD))[kp] = ((const uint32_t*)(Bh + n * 128))[kp];
        if (TERMS == 3)
            ((uint32_t*)(sBl + n * SPAD))[kp] = ((const uint32_t*)(Bl + n * 128))[kp];
    }
    if (tid < NOUT) sbias[tid] = bias ? bias[tid] : 0.f;

    // A: load fp32, split hi(/lo) bf16 into padded smem (64 rows)
    for (int i = tid; i < 64 * 64; i += 256) {
        int row = i >> 6, k = (i & 63) << 1;
        float2 a = make_float2(0.f, 0.f);
        if (r0 + row < M) a = *(const float2*)(A + (size_t)(r0 + row) * 128 + k);
        __nv_bfloat16 h0 = __float2bfloat16(a.x);
        __nv_bfloat16 h1 = __float2bfloat16(a.y);
        __nv_bfloat162 hp; hp.x = h0; hp.y = h1;
        *(__nv_bfloat162*)(sAh + row * SPAD + k) = hp;
        if (TERMS == 3) {
            __nv_bfloat162 lp;
            lp.x = __float2bfloat16(a.x - __bfloat162float(h0));
            lp.y = __float2bfloat16(a.y - __bfloat162float(h1));
            *(__nv_bfloat162*)(sAl + row * SPAD + k) = lp;
        }
    }
    __syncthreads();

    float acc[NT][4];
#pragma unroll
    for (int t = 0; t < NT; t++)
#pragma unroll
        for (int j = 0; j < 4; j++) acc[t][j] = 0.f;

    // ldmatrix base addresses (lane-dependent row/col mapping)
    uint32_t aRow = mband * 16 + (lane & 15), aCol = (lane >> 4) << 3;
    uint32_t bRow = nhalf * (NOUT / 2) + ((lane >> 4) << 3) + (lane & 7);
    uint32_t bCol = ((lane >> 3) & 1) << 3;

#pragma unroll
    for (int term = 0; term < TERMS; term++) {
        const __nv_bfloat16* pA = (term == 2) ? sAl : sAh;
        const __nv_bfloat16* pB = (term == 1) ? sBl : sBh;
        uint32_t aBase = smem_u32(pA) + (aRow * SPAD + aCol) * 2;
        uint32_t bBase = smem_u32(pB) + (bRow * SPAD + bCol) * 2;
#pragma unroll
        for (int kk = 0; kk < 8; kk++) {
            uint32_t a0, a1, a2, a3;
            asm volatile("ldmatrix.sync.aligned.m8n8.x4.shared.b16 {%0,%1,%2,%3}, [%4];"
                         : "=r"(a0), "=r"(a1), "=r"(a2), "=r"(a3)
                         : "r"(aBase + kk * 32));
#pragma unroll
            for (int np = 0; np < NT / 2; np++) {
                uint32_t b0, b1, b2, b3;
                asm volatile("ldmatrix.sync.aligned.m8n8.x4.shared.b16 {%0,%1,%2,%3}, [%4];"
                             : "=r"(b0), "=r"(b1), "=r"(b2), "=r"(b3)
                             : "r"(bBase + (np * 16 * SPAD) * 2 + kk * 32));
                asm volatile(
                    "mma.sync.aligned.m16n8k16.row.col.f32.bf16.bf16.f32 "
                    "{%0,%1,%2,%3}, {%4,%5,%6,%7}, {%8,%9}, {%0,%1,%2,%3};"
                    : "+f"(acc[np * 2][0]), "+f"(acc[np * 2][1]),
                      "+f"(acc[np * 2][2]), "+f"(acc[np * 2][3])
                    : "r"(a0), "r"(a1), "r"(a2), "r"(a3), "r"(b0), "r"(b1));
                asm volatile(
                    "mma.sync.aligned.m16n8k16.row.col.f32.bf16.bf16.f32 "
                    "{%0,%1,%2,%3}, {%4,%5,%6,%7}, {%8,%9}, {%0,%1,%2,%3};"
                    : "+f"(acc[np * 2 + 1][0]), "+f"(acc[np * 2 + 1][1]),
                      "+f"(acc[np * 2 + 1][2]), "+f"(acc[np * 2 + 1][3])
                    : "r"(a0), "r"(a1), "r"(a2), "r"(a3), "r"(b2), "r"(b3));
            }
        }
    }

    // epilogue: c fragment (r=lane/4 [+8], n=2*(lane%4)+{0,1}) per n-tile
    int rA = r0 + mband * 16 + (lane >> 2);
    int cB = 2 * (lane & 3);
#pragma unroll
    for (int t = 0; t < NT; t++) {
        int col = nhalf * (NOUT / 2) + t * 8 + cB;
        float2 u0 = make_float2(acc[t][0] + sbias[col], acc[t][1] + sbias[col + 1]);
        float2 u1 = make_float2(acc[t][2] + sbias[col], acc[t][3] + sbias[col + 1]);
        if (act == 1) {
            u0.x = fmaxf(u0.x, 0.f); u0.y = fmaxf(u0.y, 0.f);
            u1.x = fmaxf(u1.x, 0.f); u1.y = fmaxf(u1.y, 0.f);
        } else if (act == 2) {
            u0.x = tanhf(u0.x); u0.y = tanhf(u0.y);
            u1.x = tanhf(u1.x); u1.y = tanhf(u1.y);
        }
        if (rA < M)     *(float2*)(C + (size_t)rA * NOUT + col) = u0;
        if (rA + 8 < M) *(float2*)(C + (size_t)(rA + 8) * NOUT + col) = u1;
    }
}

// ---------------- edge resistance (unchanged) -----------------------------------
__global__ void __launch_bounds__(256)
edge_resist(const int* __restrict__ src, const int* __restrict__ dst,
            const float* __restrict__ b1, const float* __restrict__ w2,
            const float* __restrict__ b2) {
    int e = (blockIdx.x * blockDim.x + threadIdx.x) >> 5;
    int lane = threadIdx.x & 31;
    if (e >= EE) return;
    int s = src[e], d = dst[e];
    float4 p = *(const float4*)(g_P + (size_t)s * HH + lane * 4);
    float4 q = *(const float4*)(g_Q + (size_t)d * HH + lane * 4);
    float4 bb = *(const float4*)(b1 + lane * 4);
    float4 ww = *(const float4*)(w2 + lane * 4);
    float sum = fmaxf(p.x + q.x + bb.x, 0.f) * ww.x
              + fmaxf(p.y + q.y + bb.y, 0.f) * ww.y
              + fmaxf(p.z + q.z + bb.z, 0.f) * ww.z
              + fmaxf(p.w + q.w + bb.w, 0.f) * ww.w;
#pragma unroll
    for (int off = 16; off > 0; off >>= 1) sum += __shfl_xor_sync(0xFFFFFFFFu, sum, off);
    if (lane == 0) {
        float rr = fabsf(sum + b2[0]);
        g_r[e] = rr;
        atomicAdd(&g_deg[s], rr);
    }
}

// ---------------- scatter (unchanged) -------------------------------------------
__global__ void __launch_bounds__(256)
scatter_edges(const int* __restrict__ src, const int* __restrict__ dst) {
    int e = (blockIdx.x * blockDim.x + threadIdx.x) >> 5;
    int lane = threadIdx.x & 31;
    if (e >= EE) return;
    float rr = g_r[e];
    int s = src[e], d = dst[e];
    float4 fv = *(const float4*)(g_f + (size_t)s * HH + lane * 4);
    float* gp = g_g + (size_t)d * HH + lane * 4;
    asm volatile("red.global.add.v4.f32 [%0], {%1,%2,%3,%4};"
                 :: "l"(gp), "f"(rr * fv.x), "f"(rr * fv.y), "f"(rr * fv.z), "f"(rr * fv.w)
                 : "memory");
}

// ---------------- node update (unchanged) ---------------------------------------
__global__ void __launch_bounds__(256)
update_nodes() {
    int i4 = blockIdx.x * blockDim.x + threadIdx.x;
    if (i4 >= NN * HH / 4) return;
    int row = i4 >> 5;
    float dg = g_deg[row];
    float4 f4 = ((const float4*)g_f)[i4];
    float4 gg = ((const float4*)g_g)[i4];
    float4 ds = ((const float4*)g_d)[i4];
    float4 vv = ((const float4*)g_v)[i4];
    float4 xx = ((const float4*)g_x)[i4];
    vv.x -= EPS_ * ((dg * f4.x - gg.x) + ds.x * vv.x);
    vv.y -= EPS_ * ((dg * f4.y - gg.y) + ds.y * vv.y);
    vv.z -= EPS_ * ((dg * f4.z - gg.z) + ds.z * vv.z);
    vv.w -= EPS_ * ((dg * f4.w - gg.w) + ds.w * vv.w);
    xx.x += EPS_ * vv.x;
    xx.y += EPS_ * vv.y;
    xx.z += EPS_ * vv.z;
    xx.w += EPS_ * vv.w;
    ((float4*)g_v)[i4] = vv;
    ((float4*)g_x)[i4] = xx;
}

// ------------------------------- driver -----------------------------------------
extern "C" void kernel_launch(void* const* d_in, const int* in_sizes, int n_in,
                              void* d_out, int out_size) {
    const float* x_in   = (const float*)d_in[0];
    const int*   ei     = (const int*)  d_in[1];
    const float* emb_w  = (const float*)d_in[2];
    const float* emb_b  = (const float*)d_in[3];
    const float* lap_w  = (const float*)d_in[4];
    const float* er_w1  = (const float*)d_in[5];
    const float* er_b1  = (const float*)d_in[6];
    const float* er_w2  = (const float*)d_in[7];
    const float* er_b2  = (const float*)d_in[8];
    const float* diss_w = (const float*)d_in[9];
    const float* diss_b = (const float*)d_in[10];
    const float* mlp_w1 = (const float*)d_in[11];
    const float* mlp_b1 = (const float*)d_in[12];
    const float* mlp_w2 = (const float*)d_in[13];
    const float* mlp_b2 = (const float*)d_in[14];
    const float* ro_w   = (const float*)d_in[15];
    const float* ro_b   = (const float*)d_in[16];
    const int* src = ei;
    const int* dst = ei + EE;

    float *px, *pv, *pP, *pQ, *pf, *pd, *pg, *pdeg;
    cudaGetSymbolAddress((void**)&px, g_x);
    cudaGetSymbolAddress((void**)&pv, g_v);
    cudaGetSymbolAddress((void**)&pP, g_P);
    cudaGetSymbolAddress((void**)&pQ, g_Q);
    cudaGetSymbolAddress((void**)&pf, g_f);
    cudaGetSymbolAddress((void**)&pd, g_d);
    cudaGetSymbolAddress((void**)&pg, g_g);
    cudaGetSymbolAddress((void**)&pdeg, g_deg);
    __nv_bfloat16 *pWh, *pWl;
    cudaGetSymbolAddress((void**)&pWh, g_Wh);
    cudaGetSymbolAddress((void**)&pWl, g_Wl);

    const int SM128_3 = 1024 + 2 * 64 * SPAD * 2 + 2 * 128 * SPAD * 2;  // 105472
    const int SM128_1 = 1024 + 1 * 64 * SPAD * 2 + 1 * 128 * SPAD * 2;  // 53248
    const int SM64_3  = 1024 + 2 * 64 * SPAD * 2 + 2 * 64 * SPAD * 2;   // 70656
    cudaFuncSetAttribute((const void*)gemm_tc<128, 3>,
                         cudaFuncAttributeMaxDynamicSharedMemorySize, SM128_3);
    cudaFuncSetAttribute((const void*)gemm_tc<128, 1>,
                         cudaFuncAttributeMaxDynamicSharedMemorySize, SM128_1);
    cudaFuncSetAttribute((const void*)gemm_tc<64, 3>,
                         cudaFuncAttributeMaxDynamicSharedMemorySize, SM64_3);

    const int GT = (NN + 63) / 64;     // 782
    const int EB = EE / 8;
    const int UB = (NN * HH / 4 + 255) / 256;
#define WSLOT(s) (pWh + (s) * 16384), (pWl + (s) * 16384)

    convert_weights<<<dim3(64, 20), 256>>>(emb_w, er_w1, lap_w, diss_w, mlp_w1, mlp_w2, ro_w);

    // x = x_in @ emb_w^T + emb_b   (main path: 3-term)
    gemm_tc<128, 3><<<GT, 256, SM128_3>>>(x_in, NN, WSLOT(0), emb_b, 0, px);

    for (int b = 0; b < NB; b++) {
        int s0 = 1 + b * 6;
        // P, Q feed edge resistance -> eps^2-damped path: 1-term bf16 suffices
        gemm_tc<128, 1><<<GT, 256, SM128_1>>>(px, NN, WSLOT(s0 + 0), nullptr, 0, pP);
        gemm_tc<128, 1><<<GT, 256, SM128_1>>>(px, NN, WSLOT(s0 + 1), nullptr, 0, pQ);
        cudaMemsetAsync(pdeg, 0, NN * sizeof(float), 0);
        cudaMemsetAsync(pv, 0, (size_t)NN * HH * sizeof(float), 0);
        edge_resist<<<EB, 256>>>(src, dst, er_b1 + (size_t)b * HH,
                                 er_w2 + (size_t)b * HH, er_b2 + b);
        for (int it = 0; it < NITERS; it++) {
            // f, d enter x via eps-scaled v updates: 1-term bf16 suffices
            gemm_tc<128, 1><<<GT, 256, SM128_1>>>(px, NN, WSLOT(s0 + 2), nullptr, 0, pf);
            gemm_tc<128, 1><<<GT, 256, SM128_1>>>(px, NN, WSLOT(s0 + 3),
                                                  diss_b + (size_t)b * HH, 1, pd);
            cudaMemsetAsync(pg, 0, (size_t)NN * HH * sizeof(float), 0);
            scatter_edges<<<EB, 256>>>(src, dst);
            update_nodes<<<UB, 256>>>();
        }
        // mlp: main path, 3-term
        gemm_tc<128, 3><<<GT, 256, SM128_3>>>(px, NN, WSLOT(s0 + 4),
                                              mlp_b1 + (size_t)b * HH, 2, pP);
        gemm_tc<128, 3><<<GT, 256, SM128_3>>>(pP, NN, WSLOT(s0 + 5),
                                              mlp_b2 + (size_t)b * HH, 0, px);
    }

    gemm_tc<64, 3><<<GT, 256, SM64_3>>>(px, NN, WSLOT(19), ro_b, 0, (float*)d_out);
}

// round 14
// speedup vs baseline: 1.3893x; 1.0853x over previous
#include <cuda_runtime.h>
#include <cuda_bf16.h>
#include <cstdint>

#define NN 50000
#define EE 400000
#define HH 128
#define NB 3
#define NITERS 2
#define EPS_ 0.01f

// ---------------- scratch (device globals; no allocation allowed) ----------------
__device__ float g_x[NN * HH];
__device__ float g_v[NN * HH];
__device__ float g_P[NN * HH];
__device__ float g_Q[NN * HH];
__device__ float g_f[NN * HH];
__device__ float g_d[NN * HH];
__device__ float g_g[NN * HH];
__device__ float g_r[EE];
__device__ float g_deg[NN];
// pre-split weights, plain row-major [slot][n][k] bf16 (slot19 = readout, 64x128)
__device__ __nv_bfloat16 g_Wh[20 * 128 * 128];
__device__ __nv_bfloat16 g_Wl[20 * 128 * 128];

__device__ __forceinline__ uint32_t smem_u32(const void* p) {
    uint32_t a;
    asm("{ .reg .u64 t; cvta.to.shared.u64 t, %1; cvt.u32.u64 %0, t; }" : "=r"(a) : "l"(p));
    return a;
}

// ---------------- weight pre-split (runs once per launch) -----------------------
__global__ void convert_weights(const float* __restrict__ emb_w, const float* __restrict__ er_w1,
                                const float* __restrict__ lap_w, const float* __restrict__ diss_w,
                                const float* __restrict__ mlp_w1, const float* __restrict__ mlp_w2,
                                const float* __restrict__ ro_w) {
    int slot = blockIdx.y;
    int rows = (slot == 19) ? 64 : 128;
    int idx = blockIdx.x * 256 + threadIdx.x;
    if (idx >= rows * 128) return;
    int r = idx >> 7, k = idx & 127;
    const float* srcp;
    int wld = 128, koff = 0;
    if (slot == 0) srcp = emb_w;
    else if (slot == 19) srcp = ro_w;
    else {
        int b = (slot - 1) / 6, j = (slot - 1) % 6;
        if (j == 0)      { srcp = er_w1 + (size_t)b * 128 * 256; wld = 256; }
        else if (j == 1) { srcp = er_w1 + (size_t)b * 128 * 256; wld = 256; koff = 128; }
        else if (j == 2) srcp = lap_w  + (size_t)b * 16384;
        else if (j == 3) srcp = diss_w + (size_t)b * 16384;
        else if (j == 4) srcp = mlp_w1 + (size_t)b * 16384;
        else             srcp = mlp_w2 + (size_t)b * 16384;
    }
    float x = srcp[(size_t)r * wld + koff + k];
    __nv_bfloat16 hi = __float2bfloat16(x);
    __nv_bfloat16 lo = __float2bfloat16(x - __bfloat162float(hi));
    g_Wh[slot * 16384 + idx] = hi;
    g_Wl[slot * 16384 + idx] = lo;
}

#define SPAD 136   // smem row stride in bf16 elems (272 B -> conflict-free LDSM)

// ---------------- 3-term GEMM (main path): C = (Ah+Al) @ (Bh+Bl)^T approx --------
template <int NOUT, int TERMS>
__global__ void __launch_bounds__(256, 2)
gemm_tc(const float* __restrict__ A, int M,
        const __nv_bfloat16* __restrict__ Bh, const __nv_bfloat16* __restrict__ Bl,
        const float* __restrict__ bias, int act, float* __restrict__ C) {
    constexpr int NT = NOUT / 16;
    constexpr int NA = (TERMS == 3) ? 2 : 1;
    constexpr int A_SZ = 64 * SPAD * 2;
    constexpr int B_SZ = NOUT * SPAD * 2;
    extern __shared__ char sm[];
    float* sbias = (float*)sm;
    __nv_bfloat16* sAh = (__nv_bfloat16*)(sm + 1024);
    __nv_bfloat16* sAl = (__nv_bfloat16*)(sm + 1024 + A_SZ);
    __nv_bfloat16* sBh = (__nv_bfloat16*)(sm + 1024 + NA * A_SZ);
    __nv_bfloat16* sBl = (__nv_bfloat16*)(sm + 1024 + NA * A_SZ + B_SZ);

    int tid = threadIdx.x, wid = tid >> 5, lane = tid & 31;
    int mband = wid >> 1, nhalf = wid & 1;
    int r0 = blockIdx.x * 64;

    for (int i = tid; i < NOUT * 64; i += 256) {
        int n = i >> 6, kp = (i & 63);
        ((uint32_t*)(sBh + n * SPAD))[kp] = ((const uint32_t*)(Bh + n * 128))[kp];
        if (TERMS == 3)
            ((uint32_t*)(sBl + n * SPAD))[kp] = ((const uint32_t*)(Bl + n * 128))[kp];
    }
    if (tid < NOUT) sbias[tid] = bias ? bias[tid] : 0.f;

    for (int i = tid; i < 64 * 64; i += 256) {
        int row = i >> 6, k = (i & 63) << 1;
        float2 a = make_float2(0.f, 0.f);
        if (r0 + row < M) a = *(const float2*)(A + (size_t)(r0 + row) * 128 + k);
        __nv_bfloat16 h0 = __float2bfloat16(a.x);
        __nv_bfloat16 h1 = __float2bfloat16(a.y);
        __nv_bfloat162 hp; hp.x = h0; hp.y = h1;
        *(__nv_bfloat162*)(sAh + row * SPAD + k) = hp;
        if (TERMS == 3) {
            __nv_bfloat162 lp;
            lp.x = __float2bfloat16(a.x - __bfloat162float(h0));
            lp.y = __float2bfloat16(a.y - __bfloat162float(h1));
            *(__nv_bfloat162*)(sAl + row * SPAD + k) = lp;
        }
    }
    __syncthreads();

    float acc[NT][4];
#pragma unroll
    for (int t = 0; t < NT; t++)
#pragma unroll
        for (int j = 0; j < 4; j++) acc[t][j] = 0.f;

    uint32_t aRow = mband * 16 + (lane & 15), aCol = (lane >> 4) << 3;
    uint32_t bRow = nhalf * (NOUT / 2) + ((lane >> 4) << 3) + (lane & 7);
    uint32_t bCol = ((lane >> 3) & 1) << 3;

#pragma unroll
    for (int term = 0; term < TERMS; term++) {
        const __nv_bfloat16* pA = (term == 2) ? sAl : sAh;
        const __nv_bfloat16* pB = (term == 1) ? sBl : sBh;
        uint32_t aBase = smem_u32(pA) + (aRow * SPAD + aCol) * 2;
        uint32_t bBase = smem_u32(pB) + (bRow * SPAD + bCol) * 2;
#pragma unroll
        for (int kk = 0; kk < 8; kk++) {
            uint32_t a0, a1, a2, a3;
            asm volatile("ldmatrix.sync.aligned.m8n8.x4.shared.b16 {%0,%1,%2,%3}, [%4];"
                         : "=r"(a0), "=r"(a1), "=r"(a2), "=r"(a3)
                         : "r"(aBase + kk * 32));
#pragma unroll
            for (int np = 0; np < NT / 2; np++) {
                uint32_t b0, b1, b2, b3;
                asm volatile("ldmatrix.sync.aligned.m8n8.x4.shared.b16 {%0,%1,%2,%3}, [%4];"
                             : "=r"(b0), "=r"(b1), "=r"(b2), "=r"(b3)
                             : "r"(bBase + (np * 16 * SPAD) * 2 + kk * 32));
                asm volatile(
                    "mma.sync.aligned.m16n8k16.row.col.f32.bf16.bf16.f32 "
                    "{%0,%1,%2,%3}, {%4,%5,%6,%7}, {%8,%9}, {%0,%1,%2,%3};"
                    : "+f"(acc[np * 2][0]), "+f"(acc[np * 2][1]),
                      "+f"(acc[np * 2][2]), "+f"(acc[np * 2][3])
                    : "r"(a0), "r"(a1), "r"(a2), "r"(a3), "r"(b0), "r"(b1));
                asm volatile(
                    "mma.sync.aligned.m16n8k16.row.col.f32.bf16.bf16.f32 "
                    "{%0,%1,%2,%3}, {%4,%5,%6,%7}, {%8,%9}, {%0,%1,%2,%3};"
                    : "+f"(acc[np * 2 + 1][0]), "+f"(acc[np * 2 + 1][1]),
                      "+f"(acc[np * 2 + 1][2]), "+f"(acc[np * 2 + 1][3])
                    : "r"(a0), "r"(a1), "r"(a2), "r"(a3), "r"(b2), "r"(b3));
            }
        }
    }

    int rA = r0 + mband * 16 + (lane >> 2);
    int cB = 2 * (lane & 3);
#pragma unroll
    for (int t = 0; t < NT; t++) {
        int col = nhalf * (NOUT / 2) + t * 8 + cB;
        float2 u0 = make_float2(acc[t][0] + sbias[col], acc[t][1] + sbias[col + 1]);
        float2 u1 = make_float2(acc[t][2] + sbias[col], acc[t][3] + sbias[col + 1]);
        if (act == 1) {
            u0.x = fmaxf(u0.x, 0.f); u0.y = fmaxf(u0.y, 0.f);
            u1.x = fmaxf(u1.x, 0.f); u1.y = fmaxf(u1.y, 0.f);
        } else if (act == 2) {
            u0.x = tanhf(u0.x); u0.y = tanhf(u0.y);
            u1.x = tanhf(u1.x); u1.y = tanhf(u1.y);
        }
        if (rA < M)     *(float2*)(C + (size_t)rA * NOUT + col) = u0;
        if (rA + 8 < M) *(float2*)(C + (size_t)(rA + 8) * NOUT + col) = u1;
    }
}

// ---------------- dual-output 1-term GEMM: C1 = A@B1^T, C2 = A@B2^T --------------
// Shares the A tile/fragments across both outputs; pays the A prologue once.
// act2: 0 none, 1 relu. smem ~89 KB -> 2 CTAs/SM.
__global__ void __launch_bounds__(256, 2)
gemm_dual(const float* __restrict__ A, int M,
          const __nv_bfloat16* __restrict__ B1, const __nv_bfloat16* __restrict__ B2,
          const float* __restrict__ bias2, int act2,
          float* __restrict__ C1, float* __restrict__ C2) {
    constexpr int NT = 8;                 // n8-tiles per warp per output
    constexpr int A_SZ = 64 * SPAD * 2;
    constexpr int B_SZ = 128 * SPAD * 2;
    extern __shared__ char sm[];
    float* sbias2 = (float*)sm;                                  // [128]
    __nv_bfloat16* sA  = (__nv_bfloat16*)(sm + 1024);
    __nv_bfloat16* sB1 = (__nv_bfloat16*)(sm + 1024 + A_SZ);
    __nv_bfloat16* sB2 = (__nv_bfloat16*)(sm + 1024 + A_SZ + B_SZ);

    int tid = threadIdx.x, wid = tid >> 5, lane = tid & 31;
    int mband = wid >> 1, nhalf = wid & 1;
    int r0 = blockIdx.x * 64;

    for (int i = tid; i < 128 * 64; i += 256) {
        int n = i >> 6, kp = (i & 63);
        ((uint32_t*)(sB1 + n * SPAD))[kp] = ((const uint32_t*)(B1 + n * 128))[kp];
        ((uint32_t*)(sB2 + n * SPAD))[kp] = ((const uint32_t*)(B2 + n * 128))[kp];
    }
    if (tid < 128) sbias2[tid] = bias2 ? bias2[tid] : 0.f;

    for (int i = tid; i < 64 * 64; i += 256) {
        int row = i >> 6, k = (i & 63) << 1;
        float2 a = make_float2(0.f, 0.f);
        if (r0 + row < M) a = *(const float2*)(A + (size_t)(r0 + row) * 128 + k);
        __nv_bfloat162 hp;
        hp.x = __float2bfloat16(a.x);
        hp.y = __float2bfloat16(a.y);
        *(__nv_bfloat162*)(sA + row * SPAD + k) = hp;
    }
    __syncthreads();

    float acc1[NT][4], acc2[NT][4];
#pragma unroll
    for (int t = 0; t < NT; t++)
#pragma unroll
        for (int j = 0; j < 4; j++) { acc1[t][j] = 0.f; acc2[t][j] = 0.f; }

    uint32_t aRow = mband * 16 + (lane & 15), aCol = (lane >> 4) << 3;
    uint32_t bRow = nhalf * 64 + ((lane >> 4) << 3) + (lane & 7);
    uint32_t bCol = ((lane >> 3) & 1) << 3;
    uint32_t aBase = smem_u32(sA) + (aRow * SPAD + aCol) * 2;
    uint32_t b1Base = smem_u32(sB1) + (bRow * SPAD + bCol) * 2;
    uint32_t b2Base = smem_u32(sB2) + (bRow * SPAD + bCol) * 2;

#pragma unroll
    for (int kk = 0; kk < 8; kk++) {
        uint32_t a0, a1, a2, a3;
        asm volatile("ldmatrix.sync.aligned.m8n8.x4.shared.b16 {%0,%1,%2,%3}, [%4];"
                     : "=r"(a0), "=r"(a1), "=r"(a2), "=r"(a3)
                     : "r"(aBase + kk * 32));
#pragma unroll
        for (int np = 0; np < NT / 2; np++) {
            uint32_t b0, b1, b2, b3;
            asm volatile("ldmatrix.sync.aligned.m8n8.x4.shared.b16 {%0,%1,%2,%3}, [%4];"
                         : "=r"(b0), "=r"(b1), "=r"(b2), "=r"(b3)
                         : "r"(b1Base + (np * 16 * SPAD) * 2 + kk * 32));
            asm volatile(
                "mma.sync.aligned.m16n8k16.row.col.f32.bf16.bf16.f32 "
                "{%0,%1,%2,%3}, {%4,%5,%6,%7}, {%8,%9}, {%0,%1,%2,%3};"
                : "+f"(acc1[np * 2][0]), "+f"(acc1[np * 2][1]),
                  "+f"(acc1[np * 2][2]), "+f"(acc1[np * 2][3])
                : "r"(a0), "r"(a1), "r"(a2), "r"(a3), "r"(b0), "r"(b1));
            asm volatile(
                "mma.sync.aligned.m16n8k16.row.col.f32.bf16.bf16.f32 "
                "{%0,%1,%2,%3}, {%4,%5,%6,%7}, {%8,%9}, {%0,%1,%2,%3};"
                : "+f"(acc1[np * 2 + 1][0]), "+f"(acc1[np * 2 + 1][1]),
                  "+f"(acc1[np * 2 + 1][2]), "+f"(acc1[np * 2 + 1][3])
                : "r"(a0), "r"(a1), "r"(a2), "r"(a3), "r"(b2), "r"(b3));
            uint32_t c0, c1, c2, c3;
            asm volatile("ldmatrix.sync.aligned.m8n8.x4.shared.b16 {%0,%1,%2,%3}, [%4];"
                         : "=r"(c0), "=r"(c1), "=r"(c2), "=r"(c3)
                         : "r"(b2Base + (np * 16 * SPAD) * 2 + kk * 32));
            asm volatile(
                "mma.sync.aligned.m16n8k16.row.col.f32.bf16.bf16.f32 "
                "{%0,%1,%2,%3}, {%4,%5,%6,%7}, {%8,%9}, {%0,%1,%2,%3};"
                : "+f"(acc2[np * 2][0]), "+f"(acc2[np * 2][1]),
                  "+f"(acc2[np * 2][2]), "+f"(acc2[np * 2][3])
                : "r"(a0), "r"(a1), "r"(a2), "r"(a3), "r"(c0), "r"(c1));
            asm volatile(
                "mma.sync.aligned.m16n8k16.row.col.f32.bf16.bf16.f32 "
                "{%0,%1,%2,%3}, {%4,%5,%6,%7}, {%8,%9}, {%0,%1,%2,%3};"
                : "+f"(acc2[np * 2 + 1][0]), "+f"(acc2[np * 2 + 1][1]),
                  "+f"(acc2[np * 2 + 1][2]), "+f"(acc2[np * 2 + 1][3])
                : "r"(a0), "r"(a1), "r"(a2), "r"(a3), "r"(c2), "r"(c3));
        }
    }

    int rA = r0 + mband * 16 + (lane >> 2);
    int cB = 2 * (lane & 3);
#pragma unroll
    for (int t = 0; t < NT; t++) {
        int col = nhalf * 64 + t * 8 + cB;
        if (rA < M) {
            *(float2*)(C1 + (size_t)rA * 128 + col) = make_float2(acc1[t][0], acc1[t][1]);
        }
        if (rA + 8 < M) {
            *(float2*)(C1 + (size_t)(rA + 8) * 128 + col) = make_float2(acc1[t][2], acc1[t][3]);
        }
        float2 u0 = make_float2(acc2[t][0] + sbias2[col], acc2[t][1] + sbias2[col + 1]);
        float2 u1 = make_float2(acc2[t][2] + sbias2[col], acc2[t][3] + sbias2[col + 1]);
        if (act2 == 1) {
            u0.x = fmaxf(u0.x, 0.f); u0.y = fmaxf(u0.y, 0.f);
            u1.x = fmaxf(u1.x, 0.f); u1.y = fmaxf(u1.y, 0.f);
        }
        if (rA < M)     *(float2*)(C2 + (size_t)rA * 128 + col) = u0;
        if (rA + 8 < M) *(float2*)(C2 + (size_t)(rA + 8) * 128 + col) = u1;
    }
}

// ---------------- edge resistance (unchanged) -----------------------------------
__global__ void __launch_bounds__(256)
edge_resist(const int* __restrict__ src, const int* __restrict__ dst,
            const float* __restrict__ b1, const float* __restrict__ w2,
            const float* __restrict__ b2) {
    int e = (blockIdx.x * blockDim.x + threadIdx.x) >> 5;
    int lane = threadIdx.x & 31;
    if (e >= EE) return;
    int s = src[e], d = dst[e];
    float4 p = *(const float4*)(g_P + (size_t)s * HH + lane * 4);
    float4 q = *(const float4*)(g_Q + (size_t)d * HH + lane * 4);
    float4 bb = *(const float4*)(b1 + lane * 4);
    float4 ww = *(const float4*)(w2 + lane * 4);
    float sum = fmaxf(p.x + q.x + bb.x, 0.f) * ww.x
              + fmaxf(p.y + q.y + bb.y, 0.f) * ww.y
              + fmaxf(p.z + q.z + bb.z, 0.f) * ww.z
              + fmaxf(p.w + q.w + bb.w, 0.f) * ww.w;
#pragma unroll
    for (int off = 16; off > 0; off >>= 1) sum += __shfl_xor_sync(0xFFFFFFFFu, sum, off);
    if (lane == 0) {
        float rr = fabsf(sum + b2[0]);
        g_r[e] = rr;
        atomicAdd(&g_deg[s], rr);
    }
}

// ---------------- scatter (unchanged) -------------------------------------------
__global__ void __launch_bounds__(256)
scatter_edges(const int* __restrict__ src, const int* __restrict__ dst) {
    int e = (blockIdx.x * blockDim.x + threadIdx.x) >> 5;
    int lane = threadIdx.x & 31;
    if (e >= EE) return;
    float rr = g_r[e];
    int s = src[e], d = dst[e];
    float4 fv = *(const float4*)(g_f + (size_t)s * HH + lane * 4);
    float* gp = g_g + (size_t)d * HH + lane * 4;
    asm volatile("red.global.add.v4.f32 [%0], {%1,%2,%3,%4};"
                 :: "l"(gp), "f"(rr * fv.x), "f"(rr * fv.y), "f"(rr * fv.z), "f"(rr * fv.w)
                 : "memory");
}

// ---------------- node update (unchanged) ---------------------------------------
__global__ void __launch_bounds__(256)
update_nodes() {
    int i4 = blockIdx.x * blockDim.x + threadIdx.x;
    if (i4 >= NN * HH / 4) return;
    int row = i4 >> 5;
    float dg = g_deg[row];
    float4 f4 = ((const float4*)g_f)[i4];
    float4 gg = ((const float4*)g_g)[i4];
    float4 ds = ((const float4*)g_d)[i4];
    float4 vv = ((const float4*)g_v)[i4];
    float4 xx = ((const float4*)g_x)[i4];
    vv.x -= EPS_ * ((dg * f4.x - gg.x) + ds.x * vv.x);
    vv.y -= EPS_ * ((dg * f4.y - gg.y) + ds.y * vv.y);
    vv.z -= EPS_ * ((dg * f4.z - gg.z) + ds.z * vv.z);
    vv.w -= EPS_ * ((dg * f4.w - gg.w) + ds.w * vv.w);
    xx.x += EPS_ * vv.x;
    xx.y += EPS_ * vv.y;
    xx.z += EPS_ * vv.z;
    xx.w += EPS_ * vv.w;
    ((float4*)g_v)[i4] = vv;
    ((float4*)g_x)[i4] = xx;
}

// ------------------------------- driver -----------------------------------------
extern "C" void kernel_launch(void* const* d_in, const int* in_sizes, int n_in,
                              void* d_out, int out_size) {
    const float* x_in   = (const float*)d_in[0];
    const int*   ei     = (const int*)  d_in[1];
    const float* emb_w  = (const float*)d_in[2];
    const float* emb_b  = (const float*)d_in[3];
    const float* lap_w  = (const float*)d_in[4];
    const float* er_w1  = (const float*)d_in[5];
    const float* er_b1  = (const float*)d_in[6];
    const float* er_w2  = (const float*)d_in[7];
    const float* er_b2  = (const float*)d_in[8];
    const float* diss_w = (const float*)d_in[9];
    const float* diss_b = (const float*)d_in[10];
    const float* mlp_w1 = (const float*)d_in[11];
    const float* mlp_b1 = (const float*)d_in[12];
    const float* mlp_w2 = (const float*)d_in[13];
    const float* mlp_b2 = (const float*)d_in[14];
    const float* ro_w   = (const float*)d_in[15];
    const float* ro_b   = (const float*)d_in[16];
    const int* src = ei;
    const int* dst = ei + EE;

    float *px, *pv, *pP, *pQ, *pf, *pd, *pg, *pdeg;
    cudaGetSymbolAddress((void**)&px, g_x);
    cudaGetSymbolAddress((void**)&pv, g_v);
    cudaGetSymbolAddress((void**)&pP, g_P);
    cudaGetSymbolAddress((void**)&pQ, g_Q);
    cudaGetSymbolAddress((void**)&pf, g_f);
    cudaGetSymbolAddress((void**)&pd, g_d);
    cudaGetSymbolAddress((void**)&pg, g_g);
    cudaGetSymbolAddress((void**)&pdeg, g_deg);
    __nv_bfloat16 *pWh, *pWl;
    cudaGetSymbolAddress((void**)&pWh, g_Wh);
    cudaGetSymbolAddress((void**)&pWl, g_Wl);

    const int SM128_3 = 1024 + 2 * 64 * SPAD * 2 + 2 * 128 * SPAD * 2;  // 105472
    const int SM64_3  = 1024 + 2 * 64 * SPAD * 2 + 2 * 64 * SPAD * 2;   // 70656
    const int SMDUAL  = 1024 + 64 * SPAD * 2 + 2 * 128 * SPAD * 2;      // 88064
    cudaFuncSetAttribute((const void*)gemm_tc<128, 3>,
                         cudaFuncAttributeMaxDynamicSharedMemorySize, SM128_3);
    cudaFuncSetAttribute((const void*)gemm_tc<64, 3>,
                         cudaFuncAttributeMaxDynamicSharedMemorySize, SM64_3);
    cudaFuncSetAttribute((const void*)gemm_dual,
                         cudaFuncAttributeMaxDynamicSharedMemorySize, SMDUAL);

    const int GT = (NN + 63) / 64;     // 782
    const int EB = EE / 8;
    const int UB = (NN * HH / 4 + 255) / 256;
#define WSLOT(s) (pWh + (s) * 16384), (pWl + (s) * 16384)
#define WH(s) (pWh + (s) * 16384)

    convert_weights<<<dim3(64, 20), 256>>>(emb_w, er_w1, lap_w, diss_w, mlp_w1, mlp_w2, ro_w);

    // x = x_in @ emb_w^T + emb_b   (main path: 3-term)
    gemm_tc<128, 3><<<GT, 256, SM128_3>>>(x_in, NN, WSLOT(0), emb_b, 0, px);

    for (int b = 0; b < NB; b++) {
        int s0 = 1 + b * 6;
        // P + Q fused (1-term bf16, eps^2-damped path)
        gemm_dual<<<GT, 256, SMDUAL>>>(px, NN, WH(s0 + 0), WH(s0 + 1),
                                       nullptr, 0, pP, pQ);
        cudaMemsetAsync(pdeg, 0, NN * sizeof(float), 0);
        cudaMemsetAsync(pv, 0, (size_t)NN * HH * sizeof(float), 0);
        edge_resist<<<EB, 256>>>(src, dst, er_b1 + (size_t)b * HH,
                                 er_w2 + (size_t)b * HH, er_b2 + b);
        for (int it = 0; it < NITERS; it++) {
            // f + d fused (1-term bf16, eps-damped path); d gets bias+relu
            gemm_dual<<<GT, 256, SMDUAL>>>(px, NN, WH(s0 + 2), WH(s0 + 3),
                                           diss_b + (size_t)b * HH, 1, pf, pd);
            cudaMemsetAsync(pg, 0, (size_t)NN * HH * sizeof(float), 0);
            scatter_edges<<<EB, 256>>>(src, dst);
            update_nodes<<<UB, 256>>>();
        }
        // mlp: main path, 3-term
        gemm_tc<128, 3><<<GT, 256, SM128_3>>>(px, NN, WSLOT(s0 + 4),
                                              mlp_b1 + (size_t)b * HH, 2, pP);
        gemm_tc<128, 3><<<GT, 256, SM128_3>>>(pP, NN, WSLOT(s0 + 5),
                                              mlp_b2 + (size_t)b * HH, 0, px);
    }

    gemm_tc<64, 3><<<GT, 256, SM64_3>>>(px, NN, WSLOT(19), ro_b, 0, (float*)d_out);
}

// round 17
// speedup vs baseline: 1.4636x; 1.0535x over previous
#include <cuda_runtime.h>
#include <cuda_bf16.h>
#include <cstdint>

#define NN 50000
#define EE 400000
#define HH 128
#define NB 3
#define NITERS 2
#define EPS_ 0.01f

// ---------------- scratch (device globals; no allocation allowed) ----------------
__device__ float g_x[NN * HH];
__device__ float g_v[NN * HH];
__device__ float g_t[NN * HH];               // fp32 mlp temp
__device__ __nv_bfloat16 g_Pb[NN * HH];      // bf16 intermediates (eps-damped paths)
__device__ __nv_bfloat16 g_Qb[NN * HH];
__device__ __nv_bfloat16 g_fb[NN * HH];
__device__ __nv_bfloat16 g_db[NN * HH];
__device__ float g_g[NN * HH];
__device__ float g_r[EE];
__device__ float g_deg[NN];
// pre-split weights, plain row-major [slot][n][k] bf16 (slot19 = readout, 64x128)
__device__ __nv_bfloat16 g_Wh[20 * 128 * 128];
__device__ __nv_bfloat16 g_Wl[20 * 128 * 128];

__device__ __forceinline__ uint32_t smem_u32(const void* p) {
    uint32_t a;
    asm("{ .reg .u64 t; cvta.to.shared.u64 t, %1; cvt.u32.u64 %0, t; }" : "=r"(a) : "l"(p));
    return a;
}

// ---------------- weight pre-split (runs once per launch) -----------------------
__global__ void convert_weights(const float* __restrict__ emb_w, const float* __restrict__ er_w1,
                                const float* __restrict__ lap_w, const float* __restrict__ diss_w,
                                const float* __restrict__ mlp_w1, const float* __restrict__ mlp_w2,
                                const float* __restrict__ ro_w) {
    int slot = blockIdx.y;
    int rows = (slot == 19) ? 64 : 128;
    int idx = blockIdx.x * 256 + threadIdx.x;
    if (idx >= rows * 128) return;
    int r = idx >> 7, k = idx & 127;
    const float* srcp;
    int wld = 128, koff = 0;
    if (slot == 0) srcp = emb_w;
    else if (slot == 19) srcp = ro_w;
    else {
        int b = (slot - 1) / 6, j = (slot - 1) % 6;
        if (j == 0)      { srcp = er_w1 + (size_t)b * 128 * 256; wld = 256; }
        else if (j == 1) { srcp = er_w1 + (size_t)b * 128 * 256; wld = 256; koff = 128; }
        else if (j == 2) srcp = lap_w  + (size_t)b * 16384;
        else if (j == 3) srcp = diss_w + (size_t)b * 16384;
        else if (j == 4) srcp = mlp_w1 + (size_t)b * 16384;
        else             srcp = mlp_w2 + (size_t)b * 16384;
    }
    float x = srcp[(size_t)r * wld + koff + k];
    __nv_bfloat16 hi = __float2bfloat16(x);
    __nv_bfloat16 lo = __float2bfloat16(x - __bfloat162float(hi));
    g_Wh[slot * 16384 + idx] = hi;
    g_Wl[slot * 16384 + idx] = lo;
}

#define SPAD 136   // smem row stride in bf16 elems (272 B -> conflict-free LDSM)

// ---------------- 3-term GEMM (main path): fp32 out ----------------------------
template <int NOUT, int TERMS>
__global__ void __launch_bounds__(256, 2)
gemm_tc(const float* __restrict__ A, int M,
        const __nv_bfloat16* __restrict__ Bh, const __nv_bfloat16* __restrict__ Bl,
        const float* __restrict__ bias, int act, float* __restrict__ C) {
    constexpr int NT = NOUT / 16;
    constexpr int NA = (TERMS == 3) ? 2 : 1;
    constexpr int A_SZ = 64 * SPAD * 2;
    constexpr int B_SZ = NOUT * SPAD * 2;
    extern __shared__ char sm[];
    float* sbias = (float*)sm;
    __nv_bfloat16* sAh = (__nv_bfloat16*)(sm + 1024);
    __nv_bfloat16* sAl = (__nv_bfloat16*)(sm + 1024 + A_SZ);
    __nv_bfloat16* sBh = (__nv_bfloat16*)(sm + 1024 + NA * A_SZ);
    __nv_bfloat16* sBl = (__nv_bfloat16*)(sm + 1024 + NA * A_SZ + B_SZ);

    int tid = threadIdx.x, wid = tid >> 5, lane = tid & 31;
    int mband = wid >> 1, nhalf = wid & 1;
    int r0 = blockIdx.x * 64;

    for (int i = tid; i < NOUT * 64; i += 256) {
        int n = i >> 6, kp = (i & 63);
        ((uint32_t*)(sBh + n * SPAD))[kp] = ((const uint32_t*)(Bh + n * 128))[kp];
        if (TERMS == 3)
            ((uint32_t*)(sBl + n * SPAD))[kp] = ((const uint32_t*)(Bl + n * 128))[kp];
    }
    if (tid < NOUT) sbias[tid] = bias ? bias[tid] : 0.f;

    for (int i = tid; i < 64 * 64; i += 256) {
        int row = i >> 6, k = (i & 63) << 1;
        float2 a = make_float2(0.f, 0.f);
        if (r0 + row < M) a = *(const float2*)(A + (size_t)(r0 + row) * 128 + k);
        __nv_bfloat16 h0 = __float2bfloat16(a.x);
        __nv_bfloat16 h1 = __float2bfloat16(a.y);
        __nv_bfloat162 hp; hp.x = h0; hp.y = h1;
        *(__nv_bfloat162*)(sAh + row * SPAD + k) = hp;
        if (TERMS == 3) {
            __nv_bfloat162 lp;
            lp.x = __float2bfloat16(a.x - __bfloat162float(h0));
            lp.y = __float2bfloat16(a.y - __bfloat162float(h1));
            *(__nv_bfloat162*)(sAl + row * SPAD + k) = lp;
        }
    }
    __syncthreads();

    float acc[NT][4];
#pragma unroll
    for (int t = 0; t < NT; t++)
#pragma unroll
        for (int j = 0; j < 4; j++) acc[t][j] = 0.f;

    uint32_t aRow = mband * 16 + (lane & 15), aCol = (lane >> 4) << 3;
    uint32_t bRow = nhalf * (NOUT / 2) + ((lane >> 4) << 3) + (lane & 7);
    uint32_t bCol = ((lane >> 3) & 1) << 3;

#pragma unroll
    for (int term = 0; term < TERMS; term++) {
        const __nv_bfloat16* pA = (term == 2) ? sAl : sAh;
        const __nv_bfloat16* pB = (term == 1) ? sBl : sBh;
        uint32_t aBase = smem_u32(pA) + (aRow * SPAD + aCol) * 2;
        uint32_t bBase = smem_u32(pB) + (bRow * SPAD + bCol) * 2;
#pragma unroll
        for (int kk = 0; kk < 8; kk++) {
            uint32_t a0, a1, a2, a3;
            asm volatile("ldmatrix.sync.aligned.m8n8.x4.shared.b16 {%0,%1,%2,%3}, [%4];"
                         : "=r"(a0), "=r"(a1), "=r"(a2), "=r"(a3)
                         : "r"(aBase + kk * 32));
#pragma unroll
            for (int np = 0; np < NT / 2; np++) {
                uint32_t b0, b1, b2, b3;
                asm volatile("ldmatrix.sync.aligned.m8n8.x4.shared.b16 {%0,%1,%2,%3}, [%4];"
                             : "=r"(b0), "=r"(b1), "=r"(b2), "=r"(b3)
                             : "r"(bBase + (np * 16 * SPAD) * 2 + kk * 32));
                asm volatile(
                    "mma.sync.aligned.m16n8k16.row.col.f32.bf16.bf16.f32 "
                    "{%0,%1,%2,%3}, {%4,%5,%6,%7}, {%8,%9}, {%0,%1,%2,%3};"
                    : "+f"(acc[np * 2][0]), "+f"(acc[np * 2][1]),
                      "+f"(acc[np * 2][2]), "+f"(acc[np * 2][3])
                    : "r"(a0), "r"(a1), "r"(a2), "r"(a3), "r"(b0), "r"(b1));
                asm volatile(
                    "mma.sync.aligned.m16n8k16.row.col.f32.bf16.bf16.f32 "
                    "{%0,%1,%2,%3}, {%4,%5,%6,%7}, {%8,%9}, {%0,%1,%2,%3};"
                    : "+f"(acc[np * 2 + 1][0]), "+f"(acc[np * 2 + 1][1]),
                      "+f"(acc[np * 2 + 1][2]), "+f"(acc[np * 2 + 1][3])
                    : "r"(a0), "r"(a1), "r"(a2), "r"(a3), "r"(b2), "r"(b3));
            }
        }
    }

    int rA = r0 + mband * 16 + (lane >> 2);
    int cB = 2 * (lane & 3);
#pragma unroll
    for (int t = 0; t < NT; t++) {
        int col = nhalf * (NOUT / 2) + t * 8 + cB;
        float2 u0 = make_float2(acc[t][0] + sbias[col], acc[t][1] + sbias[col + 1]);
        float2 u1 = make_float2(acc[t][2] + sbias[col], acc[t][3] + sbias[col + 1]);
        if (act == 1) {
            u0.x = fmaxf(u0.x, 0.f); u0.y = fmaxf(u0.y, 0.f);
            u1.x = fmaxf(u1.x, 0.f); u1.y = fmaxf(u1.y, 0.f);
        } else if (act == 2) {
            u0.x = tanhf(u0.x); u0.y = tanhf(u0.y);
            u1.x = tanhf(u1.x); u1.y = tanhf(u1.y);
        }
        if (rA < M)     *(float2*)(C + (size_t)rA * NOUT + col) = u0;
        if (rA + 8 < M) *(float2*)(C + (size_t)(rA + 8) * NOUT + col) = u1;
    }
}

// ---------------- dual-output 1-term GEMM, bf16 outputs --------------------------
// C1 = A@B1^T, C2 = relu?(A@B2^T + bias2); outputs stored as bf16.
__global__ void __launch_bounds__(256, 2)
gemm_dual(const float* __restrict__ A, int M,
          const __nv_bfloat16* __restrict__ B1, const __nv_bfloat16* __restrict__ B2,
          const float* __restrict__ bias2, int act2,
          __nv_bfloat16* __restrict__ C1, __nv_bfloat16* __restrict__ C2) {
    constexpr int NT = 8;
    constexpr int A_SZ = 64 * SPAD * 2;
    constexpr int B_SZ = 128 * SPAD * 2;
    extern __shared__ char sm[];
    float* sbias2 = (float*)sm;                                  // [128]
    __nv_bfloat16* sA  = (__nv_bfloat16*)(sm + 1024);
    __nv_bfloat16* sB1 = (__nv_bfloat16*)(sm + 1024 + A_SZ);
    __nv_bfloat16* sB2 = (__nv_bfloat16*)(sm + 1024 + A_SZ + B_SZ);

    int tid = threadIdx.x, wid = tid >> 5, lane = tid & 31;
    int mband = wid >> 1, nhalf = wid & 1;
    int r0 = blockIdx.x * 64;

    for (int i = tid; i < 128 * 64; i += 256) {
        int n = i >> 6, kp = (i & 63);
        ((uint32_t*)(sB1 + n * SPAD))[kp] = ((const uint32_t*)(B1 + n * 128))[kp];
        ((uint32_t*)(sB2 + n * SPAD))[kp] = ((const uint32_t*)(B2 + n * 128))[kp];
    }
    if (tid < 128) sbias2[tid] = bias2 ? bias2[tid] : 0.f;

    for (int i = tid; i < 64 * 64; i += 256) {
        int row = i >> 6, k = (i & 63) << 1;
        float2 a = make_float2(0.f, 0.f);
        if (r0 + row < M) a = *(const float2*)(A + (size_t)(r0 + row) * 128 + k);
        __nv_bfloat162 hp;
        hp.x = __float2bfloat16(a.x);
        hp.y = __float2bfloat16(a.y);
        *(__nv_bfloat162*)(sA + row * SPAD + k) = hp;
    }
    __syncthreads();

    float acc1[NT][4], acc2[NT][4];
#pragma unroll
    for (int t = 0; t < NT; t++)
#pragma unroll
        for (int j = 0; j < 4; j++) { acc1[t][j] = 0.f; acc2[t][j] = 0.f; }

    uint32_t aRow = mband * 16 + (lane & 15), aCol = (lane >> 4) << 3;
    uint32_t bRow = nhalf * 64 + ((lane >> 4) << 3) + (lane & 7);
    uint32_t bCol = ((lane >> 3) & 1) << 3;
    uint32_t aBase = smem_u32(sA) + (aRow * SPAD + aCol) * 2;
    uint32_t b1Base = smem_u32(sB1) + (bRow * SPAD + bCol) * 2;
    uint32_t b2Base = smem_u32(sB2) + (bRow * SPAD + bCol) * 2;

#pragma unroll
    for (int kk = 0; kk < 8; kk++) {
        uint32_t a0, a1, a2, a3;
        asm volatile("ldmatrix.sync.aligned.m8n8.x4.shared.b16 {%0,%1,%2,%3}, [%4];"
                     : "=r"(a0), "=r"(a1), "=r"(a2), "=r"(a3)
                     : "r"(aBase + kk * 32));
#pragma unroll
        for (int np = 0; np < NT / 2; np++) {
            uint32_t b0, b1, b2, b3;
            asm volatile("ldmatrix.sync.aligned.m8n8.x4.shared.b16 {%0,%1,%2,%3}, [%4];"
                         : "=r"(b0), "=r"(b1), "=r"(b2), "=r"(b3)
                         : "r"(b1Base + (np * 16 * SPAD) * 2 + kk * 32));
            asm volatile(
                "mma.sync.aligned.m16n8k16.row.col.f32.bf16.bf16.f32 "
                "{%0,%1,%2,%3}, {%4,%5,%6,%7}, {%8,%9}, {%0,%1,%2,%3};"
                : "+f"(acc1[np * 2][0]), "+f"(acc1[np * 2][1]),
                  "+f"(acc1[np * 2][2]), "+f"(acc1[np * 2][3])
                : "r"(a0), "r"(a1), "r"(a2), "r"(a3), "r"(b0), "r"(b1));
            asm volatile(
                "mma.sync.aligned.m16n8k16.row.col.f32.bf16.bf16.f32 "
                "{%0,%1,%2,%3}, {%4,%5,%6,%7}, {%8,%9}, {%0,%1,%2,%3};"
                : "+f"(acc1[np * 2 + 1][0]), "+f"(acc1[np * 2 + 1][1]),
                  "+f"(acc1[np * 2 + 1][2]), "+f"(acc1[np * 2 + 1][3])
                : "r"(a0), "r"(a1), "r"(a2), "r"(a3), "r"(b2), "r"(b3));
            uint32_t c0, c1, c2, c3;
            asm volatile("ldmatrix.sync.aligned.m8n8.x4.shared.b16 {%0,%1,%2,%3}, [%4];"
                         : "=r"(c0), "=r"(c1), "=r"(c2), "=r"(c3)
                         : "r"(b2Base + (np * 16 * SPAD) * 2 + kk * 32));
            asm volatile(
                "mma.sync.aligned.m16n8k16.row.col.f32.bf16.bf16.f32 "
                "{%0,%1,%2,%3}, {%4,%5,%6,%7}, {%8,%9}, {%0,%1,%2,%3};"
                : "+f"(acc2[np * 2][0]), "+f"(acc2[np * 2][1]),
                  "+f"(acc2[np * 2][2]), "+f"(acc2[np * 2][3])
                : "r"(a0), "r"(a1), "r"(a2), "r"(a3), "r"(c0), "r"(c1));
            asm volatile(
                "mma.sync.aligned.m16n8k16.row.col.f32.bf16.bf16.f32 "
                "{%0,%1,%2,%3}, {%4,%5,%6,%7}, {%8,%9}, {%0,%1,%2,%3};"
                : "+f"(acc2[np * 2 + 1][0]), "+f"(acc2[np * 2 + 1][1]),
                  "+f"(acc2[np * 2 + 1][2]), "+f"(acc2[np * 2 + 1][3])
                : "r"(a0), "r"(a1), "r"(a2), "r"(a3), "r"(c2), "r"(c3));
        }
    }

    int rA = r0 + mband * 16 + (lane >> 2);
    int cB = 2 * (lane & 3);
#pragma unroll
    for (int t = 0; t < NT; t++) {
        int col = nhalf * 64 + t * 8 + cB;
        if (rA < M) {
            __nv_bfloat162 h;
            h.x = __float2bfloat16(acc1[t][0]);
            h.y = __float2bfloat16(acc1[t][1]);
            *(__nv_bfloat162*)(C1 + (size_t)rA * 128 + col) = h;
        }
        if (rA + 8 < M) {
            __nv_bfloat162 h;
            h.x = __float2bfloat16(acc1[t][2]);
            h.y = __float2bfloat16(acc1[t][3]);
            *(__nv_bfloat162*)(C1 + (size_t)(rA + 8) * 128 + col) = h;
        }
        float2 u0 = make_float2(acc2[t][0] + sbias2[col], acc2[t][1] + sbias2[col + 1]);
        float2 u1 = make_float2(acc2[t][2] + sbias2[col], acc2[t][3] + sbias2[col + 1]);
        if (act2 == 1) {
            u0.x = fmaxf(u0.x, 0.f); u0.y = fmaxf(u0.y, 0.f);
            u1.x = fmaxf(u1.x, 0.f); u1.y = fmaxf(u1.y, 0.f);
        }
        if (rA < M) {
            __nv_bfloat162 h;
            h.x = __float2bfloat16(u0.x);
            h.y = __float2bfloat16(u0.y);
            *(__nv_bfloat162*)(C2 + (size_t)rA * 128 + col) = h;
        }
        if (rA + 8 < M) {
            __nv_bfloat162 h;
            h.x = __float2bfloat16(u1.x);
            h.y = __float2bfloat16(u1.y);
            *(__nv_bfloat162*)(C2 + (size_t)(rA + 8) * 128 + col) = h;
        }
    }
}

// ---------------- edge resistance: bf16 P/Q gathers ------------------------------
__global__ void __launch_bounds__(256)
edge_resist(const int* __restrict__ src, const int* __restrict__ dst,
            const float* __restrict__ b1, const float* __restrict__ w2,
            const float* __restrict__ b2) {
    int e = (blockIdx.x * blockDim.x + threadIdx.x) >> 5;
    int lane = threadIdx.x & 31;
    if (e >= EE) return;
    int s = src[e], d = dst[e];
    uint2 pu = *(const uint2*)(g_Pb + (size_t)s * HH + lane * 4);
    uint2 qu = *(const uint2*)(g_Qb + (size_t)d * HH + lane * 4);
    float2 p0 = __bfloat1622float2(*(__nv_bfloat162*)&pu.x);
    float2 p1 = __bfloat1622float2(*(__nv_bfloat162*)&pu.y);
    float2 q0 = __bfloat1622float2(*(__nv_bfloat162*)&qu.x);
    float2 q1 = __bfloat1622float2(*(__nv_bfloat162*)&qu.y);
    float4 bb = *(const float4*)(b1 + lane * 4);
    float4 ww = *(const float4*)(w2 + lane * 4);
    float sum = fmaxf(p0.x + q0.x + bb.x, 0.f) * ww.x
              + fmaxf(p0.y + q0.y + bb.y, 0.f) * ww.y
              + fmaxf(p1.x + q1.x + bb.z, 0.f) * ww.z
              + fmaxf(p1.y + q1.y + bb.w, 0.f) * ww.w;
#pragma unroll
    for (int off = 16; off > 0; off >>= 1) sum += __shfl_xor_sync(0xFFFFFFFFu, sum, off);
    if (lane == 0) {
        float rr = fabsf(sum + b2[0]);
        g_r[e] = rr;
        atomicAdd(&g_deg[s], rr);
    }
}

// ---------------- scatter: bf16 f gather, fp32 atomics ---------------------------
__global__ void __launch_bounds__(256)
scatter_edges(const int* __restrict__ src, const int* __restrict__ dst) {
    int e = (blockIdx.x * blockDim.x + threadIdx.x) >> 5;
    int lane = threadIdx.x & 31;
    if (e >= EE) return;
    float rr = g_r[e];
    int s = src[e], d = dst[e];
    uint2 fu = *(const uint2*)(g_fb + (size_t)s * HH + lane * 4);
    float2 f0 = __bfloat1622float2(*(__nv_bfloat162*)&fu.x);
    float2 f1 = __bfloat1622float2(*(__nv_bfloat162*)&fu.y);
    float* gp = g_g + (size_t)d * HH + lane * 4;
    asm volatile("red.global.add.v4.f32 [%0], {%1,%2,%3,%4};"
                 :: "l"(gp), "f"(rr * f0.x), "f"(rr * f0.y), "f"(rr * f1.x), "f"(rr * f1.y)
                 : "memory");
}

// ---------------- node update: bf16 f/d reads ------------------------------------
__global__ void __launch_bounds__(256)
update_nodes() {
    int i4 = blockIdx.x * blockDim.x + threadIdx.x;
    if (i4 >= NN * HH / 4) return;
    int row = i4 >> 5;
    float dg = g_deg[row];
    uint2 fu = *(const uint2*)(g_fb + (size_t)i4 * 4);
    uint2 du = *(const uint2*)(g_db + (size_t)i4 * 4);
    float2 f0 = __bfloat1622float2(*(__nv_bfloat162*)&fu.x);
    float2 f1 = __bfloat1622float2(*(__nv_bfloat162*)&fu.y);
    float2 d0 = __bfloat1622float2(*(__nv_bfloat162*)&du.x);
    float2 d1 = __bfloat1622float2(*(__nv_bfloat162*)&du.y);
    float4 gg = ((const float4*)g_g)[i4];
    float4 vv = ((const float4*)g_v)[i4];
    float4 xx = ((const float4*)g_x)[i4];
    vv.x -= EPS_ * ((dg * f0.x - gg.x) + d0.x * vv.x);
    vv.y -= EPS_ * ((dg * f0.y - gg.y) + d0.y * vv.y);
    vv.z -= EPS_ * ((dg * f1.x - gg.z) + d1.x * vv.z);
    vv.w -= EPS_ * ((dg * f1.y - gg.w) + d1.y * vv.w);
    xx.x += EPS_ * vv.x;
    xx.y += EPS_ * vv.y;
    xx.z += EPS_ * vv.z;
    xx.w += EPS_ * vv.w;
    ((float4*)g_v)[i4] = vv;
    ((float4*)g_x)[i4] = xx;
}

// ------------------------------- driver -----------------------------------------
extern "C" void kernel_launch(void* const* d_in, const int* in_sizes, int n_in,
                              void* d_out, int out_size) {
    const float* x_in   = (const float*)d_in[0];
    const int*   ei     = (const int*)  d_in[1];
    const float* emb_w  = (const float*)d_in[2];
    const float* emb_b  = (const float*)d_in[3];
    const float* lap_w  = (const float*)d_in[4];
    const float* er_w1  = (const float*)d_in[5];
    const float* er_b1  = (const float*)d_in[6];
    const float* er_w2  = (const float*)d_in[7];
    const float* er_b2  = (const float*)d_in[8];
    const float* diss_w = (const float*)d_in[9];
    const float* diss_b = (const float*)d_in[10];
    const float* mlp_w1 = (const float*)d_in[11];
    const float* mlp_b1 = (const float*)d_in[12];
    const float* mlp_w2 = (const float*)d_in[13];
    const float* mlp_b2 = (const float*)d_in[14];
    const float* ro_w   = (const float*)d_in[15];
    const float* ro_b   = (const float*)d_in[16];
    const int* src = ei;
    const int* dst = ei + EE;

    float *px, *pv, *pt, *pg, *pdeg;
    __nv_bfloat16 *pPb, *pQb, *pfb, *pdb;
    cudaGetSymbolAddress((void**)&px, g_x);
    cudaGetSymbolAddress((void**)&pv, g_v);
    cudaGetSymbolAddress((void**)&pt, g_t);
    cudaGetSymbolAddress((void**)&pPb, g_Pb);
    cudaGetSymbolAddress((void**)&pQb, g_Qb);
    cudaGetSymbolAddress((void**)&pfb, g_fb);
    cudaGetSymbolAddress((void**)&pdb, g_db);
    cudaGetSymbolAddress((void**)&pg, g_g);
    cudaGetSymbolAddress((void**)&pdeg, g_deg);
    __nv_bfloat16 *pWh, *pWl;
    cudaGetSymbolAddress((void**)&pWh, g_Wh);
    cudaGetSymbolAddress((void**)&pWl, g_Wl);

    const int SM128_3 = 1024 + 2 * 64 * SPAD * 2 + 2 * 128 * SPAD * 2;  // 105472
    const int SM64_3  = 1024 + 2 * 64 * SPAD * 2 + 2 * 64 * SPAD * 2;   // 70656
    const int SMDUAL  = 1024 + 64 * SPAD * 2 + 2 * 128 * SPAD * 2;      // 88064
    cudaFuncSetAttribute((const void*)gemm_tc<128, 3>,
                         cudaFuncAttributeMaxDynamicSharedMemorySize, SM128_3);
    cudaFuncSetAttribute((const void*)gemm_tc<64, 3>,
                         cudaFuncAttributeMaxDynamicSharedMemorySize, SM64_3);
    cudaFuncSetAttribute((const void*)gemm_dual,
                         cudaFuncAttributeMaxDynamicSharedMemorySize, SMDUAL);

    const int GT = (NN + 63) / 64;     // 782
    const int EB = EE / 8;
    const int UB = (NN * HH / 4 + 255) / 256;
#define WSLOT(s) (pWh + (s) * 16384), (pWl + (s) * 16384)
#define WH(s) (pWh + (s) * 16384)

    convert_weights<<<dim3(64, 20), 256>>>(emb_w, er_w1, lap_w, diss_w, mlp_w1, mlp_w2, ro_w);

    // x = x_in @ emb_w^T + emb_b   (main path: 3-term)
    gemm_tc<128, 3><<<GT, 256, SM128_3>>>(x_in, NN, WSLOT(0), emb_b, 0, px);

    for (int b = 0; b < NB; b++) {
        int s0 = 1 + b * 6;
        // P + Q fused (1-term bf16 math, bf16 storage; eps^2-damped path)
        gemm_dual<<<GT, 256, SMDUAL>>>(px, NN, WH(s0 + 0), WH(s0 + 1),
                                       nullptr, 0, pPb, pQb);
        cudaMemsetAsync(pdeg, 0, NN * sizeof(float), 0);
        cudaMemsetAsync(pv, 0, (size_t)NN * HH * sizeof(float), 0);
        edge_resist<<<EB, 256>>>(src, dst, er_b1 + (size_t)b * HH,
                                 er_w2 + (size_t)b * HH, er_b2 + b);
        for (int it = 0; it < NITERS; it++) {
            // f + d fused (1-term bf16, bf16 storage; eps-damped path)
            gemm_dual<<<GT, 256, SMDUAL>>>(px, NN, WH(s0 + 2), WH(s0 + 3),
                                           diss_b + (size_t)b * HH, 1, pfb, pdb);
            cudaMemsetAsync(pg, 0, (size_t)NN * HH * sizeof(float), 0);
            scatter_edges<<<EB, 256>>>(src, dst);
            update_nodes<<<UB, 256>>>();
        }
        // mlp: main path, 3-term fp32 (g_t as temp)
        gemm_tc<128, 3><<<GT, 256, SM128_3>>>(px, NN, WSLOT(s0 + 4),
                                              mlp_b1 + (size_t)b * HH, 2, pt);
        gemm_tc<128, 3><<<GT, 256, SM128_3>>>(pt, NN, WSLOT(s0 + 5),
                                              mlp_b2 + (size_t)b * HH, 0, px);
    }

    gemm_tc<64, 3><<<GT, 256, SM64_3>>>(px, NN, WSLOT(19), ro_b, 0, (float*)d_out);
}